// round 4
// baseline (speedup 1.0000x reference)
#include <cuda_runtime.h>
#include <math.h>

// Problem constants
#define BB 512
#define LL 25
#define EE 300
#define HH 1024
#define DD 256
#define TT 128
#define BL (BB*LL)          // 12800
#define CATW (DD+HH)        // 1280

typedef unsigned long long ull_t;

// ---------------- scratch (device globals; no allocation allowed) -----------
__device__ float g_x[BL*EE];                    // renormed encoder embeddings
__device__ float g_gi_all[BL*3*HH];             // (B*L, 3H) input gates, all steps
__device__ float g_enc_out[BL*HH];              // (B*L, H) encoder outputs
__device__ float g_h[BB*HH];                    // recurrent hidden
__device__ float g_gh[2*BB*3*HH];               // h @ Whh^T (up to 2 split-K parts)
__device__ float g_cat[BB*CATW];                // [emb | applied]
__device__ float g_combp[4*BB*HH];              // comb GEMM split-K partials
__device__ float g_gi_dec[BB*3*HH];             // decoder input gates
__device__ int   g_inp[BB];

__device__ __forceinline__ float sigmoidf_(float x) { return 1.f/(1.f+expf(-x)); }

// packed f32x2 FMA: d = a*b + d  (ptxas never emits FFMA2 from C++)
__device__ __forceinline__ void ffma2(float2& d, const float2& a, const float2& b) {
    asm("fma.rn.f32x2 %0, %1, %2, %0;"
        : "+l"(*reinterpret_cast<ull_t*>(&d))
        : "l"(*reinterpret_cast<const ull_t*>(&a)),
          "l"(*reinterpret_cast<const ull_t*>(&b)));
}

__device__ __forceinline__ float4 ldg4_guard(const float* p, int rem) {
    if (rem >= 4) return *(const float4*)p;
    float4 v = make_float4(0.f,0.f,0.f,0.f);
    if (rem > 0) v.x = p[0];
    if (rem > 1) v.y = p[1];
    if (rem > 2) v.z = p[2];
    return v;
}

// ---------------- SGEMM (NT), 256 threads, split-K capable ------------------
// C_part[z](M,N) = A(M, kstart:kstart+klen) * B(N, kstart:kstart+klen)^T
// grid = (N/64, M/64, nsplit); kstart = z*kchunk. EPI_BIAS only with nsplit=1.
enum { EPI_NONE=0, EPI_BIAS=1 };

template<int EPI>
__global__ __launch_bounds__(256) void sgemm_k(
    const float* __restrict__ A, const float* __restrict__ Bm, float* __restrict__ C,
    int M, int N, int Kld, int kchunk, int Ktotal,
    const float* __restrict__ bias)
{
    constexpr int BM=64, BN=64, BK=16, PAD=4;
    __shared__ float As[2][BK][BM+PAD];
    __shared__ float Bs[2][BK][BN+PAD];

    const int z      = blockIdx.z;
    const int kstart = z * kchunk;
    int klen = Ktotal - kstart; if (klen > kchunk) klen = kchunk;
    C += (size_t)z * M * N;

    const int tid  = threadIdx.x;
    const int m0   = blockIdx.y * BM;
    const int n0   = blockIdx.x * BN;
    const int tcol = tid & 15;        // 16 cols of 4
    const int trow = tid >> 4;        // 16 rows of 4
    const int lr   = tid >> 2;        // 0..63 staging row
    const int lc   = (tid & 3) << 2;  // 0,4,8,12 staging k-offset

    float2 acc[2][4];
    #pragma unroll
    for (int i=0;i<2;i++)
        #pragma unroll
        for (int j=0;j<4;j++) acc[i][j] = make_float2(0.f,0.f);

    float4 ra, rb;
    auto ldg_tiles = [&](int k0) {
        int rem = klen - (k0 + lc);
        ra = ldg4_guard(A  + (size_t)(m0+lr)*Kld + kstart + k0 + lc, rem);
        rb = ldg4_guard(Bm + (size_t)(n0+lr)*Kld + kstart + k0 + lc, rem);
    };
    auto sts_tiles = [&](int buf) {
        As[buf][lc+0][lr]=ra.x; As[buf][lc+1][lr]=ra.y;
        As[buf][lc+2][lr]=ra.z; As[buf][lc+3][lr]=ra.w;
        Bs[buf][lc+0][lr]=rb.x; Bs[buf][lc+1][lr]=rb.y;
        Bs[buf][lc+2][lr]=rb.z; Bs[buf][lc+3][lr]=rb.w;
    };

    ldg_tiles(0);
    sts_tiles(0);
    __syncthreads();

    int buf = 0;
    const int nk = (klen + BK - 1) / BK;
    for (int it = 0; it < nk; it++) {
        if (it + 1 < nk) ldg_tiles((it+1)*BK);
        float (*as)[BM+PAD] = As[buf];
        float (*bs)[BN+PAD] = Bs[buf];
        #pragma unroll
        for (int kk=0; kk<BK; kk++) {
            float4 av = *(const float4*)&as[kk][trow*4];
            float4 bv = *(const float4*)&bs[kk][tcol*4];
            float2 ap[2] = { make_float2(av.x,av.y), make_float2(av.z,av.w) };
            float bj[4] = {bv.x, bv.y, bv.z, bv.w};
            #pragma unroll
            for (int j=0;j<4;j++) {
                float2 bb = make_float2(bj[j], bj[j]);
                ffma2(acc[0][j], ap[0], bb);
                ffma2(acc[1][j], ap[1], bb);
            }
        }
        if (it + 1 < nk) {
            sts_tiles(buf ^ 1);
            __syncthreads();
            buf ^= 1;
        }
    }

    float bsv[4] = {0.f,0.f,0.f,0.f};
    if (EPI == EPI_BIAS) {
        #pragma unroll
        for (int j=0;j<4;j++) bsv[j] = bias[n0 + tcol*4 + j];
    }
    #pragma unroll
    for (int i=0;i<2;i++) {
        #pragma unroll
        for (int pm=0;pm<2;pm++) {
            int m = m0 + trow*4 + i*2 + pm;
            float4 v;
            v.x = (pm ? acc[i][0].y : acc[i][0].x) + bsv[0];
            v.y = (pm ? acc[i][1].y : acc[i][1].x) + bsv[1];
            v.z = (pm ? acc[i][2].y : acc[i][2].x) + bsv[2];
            v.w = (pm ? acc[i][3].y : acc[i][3].x) + bsv[3];
            *(float4*)(C + (size_t)m*N + n0 + tcol*4) = v;
        }
    }
}

// ---- decoder merged GEMM: z=0: gi = o @ dec_Wih^T where o is reconstructed
//      on the fly as relu(bn2(sum of 4 comb partials + comb_b)); z=1: gh = h @ dec_Whh^T.
__global__ __launch_bounds__(256) void gigh_kernel(
    const float* __restrict__ combp, const float* __restrict__ comb_b,
    const float* __restrict__ bn2,
    const float* __restrict__ h,
    const float* __restrict__ Wih, const float* __restrict__ Whh,
    float* __restrict__ gi_out, float* __restrict__ gh_out)
{
    constexpr int BM=64, BN=64, BK=16, PAD=4;
    constexpr int K = HH, N = 3*HH;
    __shared__ float As[2][BK][BM+PAD];
    __shared__ float Bs[2][BK][BN+PAD];

    const bool gi_mode = (blockIdx.z == 0);
    const float* Bm = gi_mode ? Wih : Whh;
    float* C = gi_mode ? gi_out : gh_out;

    float s2=0.f, mu2=0.f, be2=0.f;
    if (gi_mode) { s2 = bn2[0]*rsqrtf(bn2[3]+1e-5f); mu2 = bn2[2]; be2 = bn2[1]; }

    const int tid  = threadIdx.x;
    const int m0   = blockIdx.y * BM;
    const int n0   = blockIdx.x * BN;
    const int tcol = tid & 15;
    const int trow = tid >> 4;
    const int lr   = tid >> 2;
    const int lc   = (tid & 3) << 2;

    float2 acc[2][4];
    #pragma unroll
    for (int i=0;i<2;i++)
        #pragma unroll
        for (int j=0;j<4;j++) acc[i][j] = make_float2(0.f,0.f);

    float4 ra, rb;
    auto ldg_tiles = [&](int k0) {
        int kk = k0 + lc;
        if (gi_mode) {
            size_t off = (size_t)(m0+lr)*HH + kk;
            float4 p0 = *(const float4*)(combp + off);
            float4 p1 = *(const float4*)(combp + (size_t)BB*HH + off);
            float4 p2 = *(const float4*)(combp + (size_t)2*BB*HH + off);
            float4 p3 = *(const float4*)(combp + (size_t)3*BB*HH + off);
            float4 cb = *(const float4*)(comb_b + kk);
            ra.x = fmaxf((p0.x+p1.x+p2.x+p3.x+cb.x - mu2)*s2 + be2, 0.f);
            ra.y = fmaxf((p0.y+p1.y+p2.y+p3.y+cb.y - mu2)*s2 + be2, 0.f);
            ra.z = fmaxf((p0.z+p1.z+p2.z+p3.z+cb.z - mu2)*s2 + be2, 0.f);
            ra.w = fmaxf((p0.w+p1.w+p2.w+p3.w+cb.w - mu2)*s2 + be2, 0.f);
        } else {
            ra = *(const float4*)(h + (size_t)(m0+lr)*HH + kk);
        }
        rb = *(const float4*)(Bm + (size_t)(n0+lr)*K + kk);
    };
    auto sts_tiles = [&](int buf) {
        As[buf][lc+0][lr]=ra.x; As[buf][lc+1][lr]=ra.y;
        As[buf][lc+2][lr]=ra.z; As[buf][lc+3][lr]=ra.w;
        Bs[buf][lc+0][lr]=rb.x; Bs[buf][lc+1][lr]=rb.y;
        Bs[buf][lc+2][lr]=rb.z; Bs[buf][lc+3][lr]=rb.w;
    };

    ldg_tiles(0);
    sts_tiles(0);
    __syncthreads();

    int buf = 0;
    const int nk = K / BK;
    for (int it = 0; it < nk; it++) {
        if (it + 1 < nk) ldg_tiles((it+1)*BK);
        float (*as)[BM+PAD] = As[buf];
        float (*bs)[BN+PAD] = Bs[buf];
        #pragma unroll
        for (int kk=0; kk<BK; kk++) {
            float4 av = *(const float4*)&as[kk][trow*4];
            float4 bv = *(const float4*)&bs[kk][tcol*4];
            float2 ap[2] = { make_float2(av.x,av.y), make_float2(av.z,av.w) };
            float bj[4] = {bv.x, bv.y, bv.z, bv.w};
            #pragma unroll
            for (int j=0;j<4;j++) {
                float2 bb = make_float2(bj[j], bj[j]);
                ffma2(acc[0][j], ap[0], bb);
                ffma2(acc[1][j], ap[1], bb);
            }
        }
        if (it + 1 < nk) {
            sts_tiles(buf ^ 1);
            __syncthreads();
            buf ^= 1;
        }
    }

    #pragma unroll
    for (int i=0;i<2;i++) {
        #pragma unroll
        for (int pm=0;pm<2;pm++) {
            int m = m0 + trow*4 + i*2 + pm;
            float4 v;
            v.x = pm ? acc[i][0].y : acc[i][0].x;
            v.y = pm ? acc[i][1].y : acc[i][1].x;
            v.z = pm ? acc[i][2].y : acc[i][2].x;
            v.w = pm ? acc[i][3].y : acc[i][3].x;
            *(float4*)(C + (size_t)m*N + n0 + tcol*4) = v;
        }
    }
}

// ---------------- small / fused kernels -------------------------------------
__global__ void init_kernel()
{
    int idx = blockIdx.x*blockDim.x + threadIdx.x;
    if (idx < BB*HH) g_h[idx] = 0.f;
    if (idx < BB)    g_inp[idx] = TT;     // SOS token = tagset_size
}

// encoder embedding lookup + max_norm=10 renorm
__global__ void embed_renorm_kernel(const int* __restrict__ tokens,
                                    const float* __restrict__ w2v)
{
    int row = blockIdx.x;
    int tok = tokens[row];
    const float* src = w2v + (size_t)tok*EE;
    __shared__ float red[128];
    float ss = 0.f;
    for (int k = threadIdx.x; k < EE; k += blockDim.x) { float v = src[k]; ss += v*v; }
    red[threadIdx.x] = ss; __syncthreads();
    for (int s = blockDim.x>>1; s>0; s>>=1) {
        if (threadIdx.x < s) red[threadIdx.x] += red[threadIdx.x+s];
        __syncthreads();
    }
    float sc = fminf(1.f, 10.f/(sqrtf(red[0])+1e-7f));
    for (int k = threadIdx.x; k < EE; k += blockDim.x)
        g_x[(size_t)row*EE + k] = src[k]*sc;
}

// GRU cell: gi parts (optional second part / bias), gh parts (optional second)
__global__ void gru_kernel(const float* __restrict__ gi0, const float* __restrict__ gi1,
                           int gi_stride, const float* __restrict__ bih,
                           const float* __restrict__ gh0, const float* __restrict__ gh1,
                           const float* __restrict__ bhh,
                           float* __restrict__ h,
                           float* __restrict__ outp, int out_stride)
{
    int idx = blockIdx.x*blockDim.x + threadIdx.x;
    if (idx >= BB*HH) return;
    int b = idx / HH, j = idx - b*HH;
    const float* p = gi0 + (size_t)b*gi_stride;
    float i_r = p[j], i_z = p[HH+j], i_n = p[2*HH+j];
    if (gi1) { const float* q = gi1 + (size_t)b*gi_stride; i_r+=q[j]; i_z+=q[HH+j]; i_n+=q[2*HH+j]; }
    if (bih) { i_r += bih[j]; i_z += bih[HH+j]; i_n += bih[2*HH+j]; }
    const float* r0 = gh0 + (size_t)b*3*HH;
    float h_r = r0[j], h_z = r0[HH+j], h_n = r0[2*HH+j];
    if (gh1) { const float* r1 = gh1 + (size_t)b*3*HH; h_r+=r1[j]; h_z+=r1[HH+j]; h_n+=r1[2*HH+j]; }
    h_r += bhh[j]; h_z += bhh[HH+j]; h_n += bhh[2*HH+j];
    float r = sigmoidf_(i_r + h_r);
    float z = sigmoidf_(i_z + h_z);
    float n = tanhf(i_n + r*h_n);
    float hv = h[idx];
    float hn = (1.f - z)*n + z*hv;
    h[idx] = hn;
    if (outp) outp[(size_t)b*out_stride + j] = hn;
}

// fused: decoder embedding (+renorm) -> attention scores -> softmax -> applied
__global__ __launch_bounds__(256) void dec_attn_kernel(
    const float* __restrict__ dec_emb,
    const float* __restrict__ attn_W, const float* __restrict__ attn_b)
{
    int b = blockIdx.x, tid = threadIdx.x;
    __shared__ float semb[DD];
    __shared__ float sh[HH];
    __shared__ float saw[32];
    __shared__ float red[256];

    int tok = g_inp[b];
    float val = dec_emb[(size_t)tok*DD + tid];
    red[tid] = val*val; __syncthreads();
    for (int s=128; s>0; s>>=1) { if (tid<s) red[tid]+=red[tid+s]; __syncthreads(); }
    float sc = fminf(1.f, 1.f/(sqrtf(red[0])+1e-7f));
    float e = val*sc;
    semb[tid] = e;
    g_cat[(size_t)b*CATW + tid] = e;
    for (int k = tid; k < HH; k += 256) sh[k] = g_h[(size_t)b*HH + k];
    __syncthreads();

    int warp = tid>>5, lane = tid&31;
    for (int l = warp; l < LL; l += 8) {
        const float* w = attn_W + (size_t)l*CATW;
        float acc = 0.f;
        for (int k = lane; k < DD; k += 32) acc += semb[k]*w[k];
        for (int k = lane; k < HH; k += 32) acc += sh[k]*w[DD+k];
        for (int o=16;o;o>>=1) acc += __shfl_xor_sync(0xffffffffu, acc, o);
        if (lane==0) saw[l] = acc + attn_b[l];
    }
    __syncthreads();
    if (warp==0) {
        float v = (lane<LL)? saw[lane] : -1e30f;
        float m = v;
        for (int o=16;o;o>>=1) m = fmaxf(m, __shfl_xor_sync(0xffffffffu, m, o));
        float ex = (lane<LL)? expf(v-m) : 0.f;
        float sm = ex;
        for (int o=16;o;o>>=1) sm += __shfl_xor_sync(0xffffffffu, sm, o);
        if (lane<LL) saw[lane] = ex/sm;
    }
    __syncthreads();

    const float* eo = g_enc_out + (size_t)b*LL*HH;
    for (int j = tid; j < HH; j += 256) {
        float acc = 0.f;
        #pragma unroll
        for (int l=0;l<LL;l++) acc += saw[l]*eo[(size_t)l*HH + j];
        g_cat[(size_t)b*CATW + DD + j] = acc;
    }
}

// fused: bn1(h) @ out_W^T + out_b -> log_softmax -> argmax -> next input
__global__ __launch_bounds__(256) void out_lsm_kernel(
    const float* __restrict__ Wt, const float* __restrict__ ob,
    const float* __restrict__ bn, float* __restrict__ out, int t)
{
    constexpr int CH = 64;
    __shared__ float hsh[HH];
    __shared__ float Ws[TT][CH+1];
    __shared__ float red[256];
    __shared__ int   redi[128];

    int b = blockIdx.x, tid = threadIdx.x;
    int v = tid & 127, half = tid >> 7;
    float s = bn[0]*rsqrtf(bn[3]+1e-5f), mu = bn[2], beta = bn[1];
    for (int k = tid; k < HH; k += 256)
        hsh[k] = (g_h[(size_t)b*HH + k] - mu)*s + beta;

    float acc = 0.f;
    for (int k0 = 0; k0 < HH; k0 += CH) {
        __syncthreads();
        for (int i = tid; i < TT*CH; i += 256) {
            int r = i >> 6, c = i & 63;
            Ws[r][c] = Wt[(size_t)r*HH + k0 + c];
        }
        __syncthreads();
        const int kb = half*32;
        #pragma unroll
        for (int k = 0; k < 32; k++)
            acc += hsh[k0 + kb + k] * Ws[v][kb + k];
    }
    __syncthreads();
    red[tid] = acc; __syncthreads();
    float x = 0.f;
    if (tid < 128) x = red[tid] + red[tid+128] + ob[tid];
    __syncthreads();
    if (tid < 128) { red[tid] = x; redi[tid] = tid; }
    __syncthreads();
    for (int st = 64; st > 0; st >>= 1) {
        if (tid < st) {
            if (red[tid+st] > red[tid]) { red[tid]=red[tid+st]; redi[tid]=redi[tid+st]; }
        }
        __syncthreads();
    }
    float m = red[0]; int am = redi[0];
    __syncthreads();
    red[tid] = (tid < 128) ? expf(x - m) : 0.f;
    __syncthreads();
    for (int st = 128; st > 0; st >>= 1) { if (tid<st) red[tid]+=red[tid+st]; __syncthreads(); }
    float lse = logf(red[0]);
    if (tid < 128) out[((size_t)b*LL + t)*TT + tid] = x - m - lse;
    if (tid == 0) g_inp[b] = am;
}

// ---------------- launch ----------------------------------------------------
extern "C" void kernel_launch(void* const* d_in, const int* in_sizes, int n_in,
                              void* d_out, int out_size)
{
    const int*   tokens  = (const int*)  d_in[0];
    const float* w2v     = (const float*)d_in[1];
    const float* enc_Wih = (const float*)d_in[2];
    const float* enc_Whh = (const float*)d_in[3];
    const float* enc_bih = (const float*)d_in[4];
    const float* enc_bhh = (const float*)d_in[5];
    const float* dec_emb = (const float*)d_in[6];
    const float* attn_W  = (const float*)d_in[7];
    const float* attn_b  = (const float*)d_in[8];
    const float* comb_W  = (const float*)d_in[9];
    const float* comb_b  = (const float*)d_in[10];
    const float* dec_Wih = (const float*)d_in[11];
    const float* dec_Whh = (const float*)d_in[12];
    const float* dec_bih = (const float*)d_in[13];
    const float* dec_bhh = (const float*)d_in[14];
    const float* out_W   = (const float*)d_in[15];
    const float* out_b   = (const float*)d_in[16];
    const float* bn1     = (const float*)d_in[17];
    const float* bn2     = (const float*)d_in[18];
    float* out = (float*)d_out;

    float *px, *pgi_all, *penc_out, *ph, *pgh, *pcat, *pcombp, *pgi_dec;
    cudaGetSymbolAddress((void**)&px,       g_x);
    cudaGetSymbolAddress((void**)&pgi_all,  g_gi_all);
    cudaGetSymbolAddress((void**)&penc_out, g_enc_out);
    cudaGetSymbolAddress((void**)&ph,       g_h);
    cudaGetSymbolAddress((void**)&pgh,      g_gh);
    cudaGetSymbolAddress((void**)&pcat,     g_cat);
    cudaGetSymbolAddress((void**)&pcombp,   g_combp);
    cudaGetSymbolAddress((void**)&pgi_dec,  g_gi_dec);

    const int EW = 2048;   // blocks for B*H elementwise at 256 threads

    init_kernel<<<EW, 256>>>();

    // encoder embeddings + input-gate GEMM for all steps
    embed_renorm_kernel<<<BL, 128>>>(tokens, w2v);
    sgemm_k<EPI_BIAS><<<dim3(3*HH/64, BL/64, 1), 256>>>(
        px, enc_Wih, pgi_all, BL, 3*HH, EE, EE, EE, enc_bih);

    // encoder recurrence (gh split-K=2 -> 768 blocks)
    for (int t = 0; t < LL; t++) {
        sgemm_k<EPI_NONE><<<dim3(3*HH/64, BB/64, 2), 256>>>(
            ph, enc_Whh, pgh, BB, 3*HH, HH, HH/2, HH, nullptr);
        gru_kernel<<<EW, 256>>>(pgi_all + (size_t)t*3*HH, nullptr, LL*3*HH, nullptr,
                                pgh, pgh + (size_t)BB*3*HH, enc_bhh,
                                ph, penc_out + (size_t)t*HH, LL*HH);
    }

    // greedy attention decoder
    for (int t = 0; t < LL; t++) {
        dec_attn_kernel<<<BB, 256>>>(dec_emb, attn_W, attn_b);
        // comb GEMM split-K=4 partials (bias+bn+relu folded into gigh A-load)
        sgemm_k<EPI_NONE><<<dim3(HH/64, BB/64, 4), 256>>>(
            pcat, comb_W, pcombp, BB, HH, CATW, CATW/4, CATW, nullptr);
        // merged gi+gh GEMMs (768 blocks)
        gigh_kernel<<<dim3(3*HH/64, BB/64, 2), 256>>>(
            pcombp, comb_b, bn2, ph, dec_Wih, dec_Whh, pgi_dec, pgh);
        gru_kernel<<<EW, 256>>>(pgi_dec, nullptr, 3*HH, dec_bih,
                                pgh, nullptr, dec_bhh, ph, nullptr, 0);
        out_lsm_kernel<<<BB, 256>>>(out_W, out_b, bn1, out, t);
    }
}

// round 6
// speedup vs baseline: 1.5256x; 1.5256x over previous
#include <cuda_runtime.h>
#include <cuda_bf16.h>
#include <math.h>
#include <stdint.h>

// Problem constants
#define BB 512
#define LL 25
#define EE 300
#define EEP 320          // padded K for encoder input GEMM (multiple of 64)
#define HH 1024
#define DD 256
#define TT 128
#define BL (BB*LL)       // 12800
#define CATW (DD+HH)     // 1280

// ---------------- scratch (device globals; no allocation allowed) -----------
__device__ __nv_bfloat16 g_x_hi[BL*EEP], g_x_lo[BL*EEP];
__device__ float g_gi_all[BL*3*HH];
__device__ float g_enc_out[BL*HH];
__device__ float g_h[BB*HH];
__device__ __nv_bfloat16 g_h_hi[BB*HH], g_h_lo[BB*HH];
__device__ float g_gh[BB*3*HH];
__device__ __nv_bfloat16 g_cat_hi[BB*CATW], g_cat_lo[BB*CATW];
__device__ __nv_bfloat16 g_o_hi[BB*HH], g_o_lo[BB*HH];
__device__ float g_gi_dec[BB*3*HH];
__device__ int   g_inp[BB];
// pre-split weights (hi/lo bf16)
__device__ __nv_bfloat16 g_wencih_hi[3*HH*EEP], g_wencih_lo[3*HH*EEP];
__device__ __nv_bfloat16 g_wenchh_hi[3*HH*HH],  g_wenchh_lo[3*HH*HH];
__device__ __nv_bfloat16 g_wdecih_hi[3*HH*HH],  g_wdecih_lo[3*HH*HH];
__device__ __nv_bfloat16 g_wdechh_hi[3*HH*HH],  g_wdechh_lo[3*HH*HH];
__device__ __nv_bfloat16 g_wcomb_hi[HH*CATW],   g_wcomb_lo[HH*CATW];

__device__ __forceinline__ float sigmoidf_(float x) { return 1.f/(1.f+expf(-x)); }

__device__ __forceinline__ uint32_t smem_u32(const void* p) {
    uint32_t a;
    asm("{ .reg .u64 t; cvta.to.shared.u64 t, %1; cvt.u32.u64 %0, t; }" : "=r"(a) : "l"(p));
    return a;
}

#define LDM4(r, addr) \
    asm volatile("ldmatrix.sync.aligned.m8n8.x4.shared.b16 {%0,%1,%2,%3}, [%4];" \
        : "=r"((r)[0]), "=r"((r)[1]), "=r"((r)[2]), "=r"((r)[3]) : "r"(addr))

#define MMA16816(d, a, b) \
    asm volatile("mma.sync.aligned.m16n8k16.row.col.f32.bf16.bf16.f32 " \
        "{%0,%1,%2,%3}, {%4,%5,%6,%7}, {%8,%9}, {%0,%1,%2,%3};" \
        : "+f"((d)[0]), "+f"((d)[1]), "+f"((d)[2]), "+f"((d)[3]) \
        : "r"((a)[0]), "r"((a)[1]), "r"((a)[2]), "r"((a)[3]), "r"((b)[0]), "r"((b)[1]))

#define CPASYNC16(dst, src) \
    asm volatile("cp.async.cg.shared.global [%0], [%1], 16;" :: "r"(dst), "l"(src))

// ---------------- HMMA bf16 3-term split GEMM --------------------------------
// C(M,N) = A(M,K)*B(N,K)^T, A~Ahi+Alo, B~Bhi+Blo (bf16 splits of fp32).
// CTA 128x128, BK=64, 256 threads (8 warps: 2 m x 4 n, 64x32 each).
// EPI=0: C fp32.  EPI=1 (comb): relu(bn2(v+bias)) -> split bf16 Ohi/Olo (ld=HH).
enum { EPI_C=0, EPI_COMB=1 };

template<int EPI>
__global__ __launch_bounds__(256) void mma_gemm(
    const __nv_bfloat16* __restrict__ Ahi, const __nv_bfloat16* __restrict__ Alo, int lda,
    const __nv_bfloat16* __restrict__ Bhi, const __nv_bfloat16* __restrict__ Blo, int ldb,
    int K, float* __restrict__ Cf, int N,
    const float* __restrict__ bias, const float* __restrict__ bn,
    __nv_bfloat16* __restrict__ Ohi, __nv_bfloat16* __restrict__ Olo)
{
    extern __shared__ char sm[];
    const int tid  = threadIdx.x;
    const int lane = tid & 31, wid = tid >> 5;
    const int wm   = wid & 1;          // 2 warp-rows of 64
    const int wn   = wid >> 1;         // 4 warp-cols of 32
    const int m0   = blockIdx.y * 128, n0 = blockIdx.x * 128;
    const uint32_t sbase = smem_u32(sm);

    // staging: thread t -> row sr (0..127), half sh (k granules sh*4..sh*4+3)
    const int sr = tid >> 1, sh = tid & 1;
    const __nv_bfloat16* tsrc[4];
    tsrc[0] = Ahi + (size_t)(m0 + sr) * lda;
    tsrc[1] = Alo + (size_t)(m0 + sr) * lda;
    tsrc[2] = Bhi + (size_t)(n0 + sr) * ldb;
    tsrc[3] = Blo + (size_t)(n0 + sr) * ldb;
    const uint32_t swrow = (uint32_t)(sr & 7);

    auto stage = [&](int buf, int k0) {
        uint32_t dbase = sbase + (uint32_t)buf * 65536u + (uint32_t)sr * 128u;
        #pragma unroll
        for (int t = 0; t < 4; t++) {
            const __nv_bfloat16* s = tsrc[t] + k0 + sh * 32;
            uint32_t db = dbase + (uint32_t)t * 16384u;
            #pragma unroll
            for (int c = 0; c < 4; c++) {
                uint32_t g = (uint32_t)(sh * 4 + c);
                uint32_t dst = db + ((g ^ swrow) << 4);
                CPASYNC16(dst, s + c * 8);
            }
        }
        asm volatile("cp.async.commit_group;" ::: "memory");
    };

    float acc[4][4][4];
    #pragma unroll
    for (int i = 0; i < 4; i++)
        #pragma unroll
        for (int j = 0; j < 4; j++)
            #pragma unroll
            for (int q = 0; q < 4; q++) acc[i][j][q] = 0.f;

    const int nt = K / 64;
    stage(0, 0);
    for (int it = 0; it < nt; it++) {
        if (it + 1 < nt) {
            stage((it + 1) & 1, (it + 1) * 64);
            asm volatile("cp.async.wait_group 1;" ::: "memory");
        } else {
            asm volatile("cp.async.wait_group 0;" ::: "memory");
        }
        __syncthreads();

        uint32_t tb = sbase + (uint32_t)(it & 1) * 65536u;
        #pragma unroll
        for (int ks = 0; ks < 4; ks++) {
            const int g0 = ks * 2;
            // A fragments (hi & lo), 4 m-tiles
            uint32_t ah[4][4], al[4][4];
            {
                int row_off = ((lane >> 3) & 1) * 8 + (lane & 7);
                int g = g0 + (lane >> 4);
                #pragma unroll
                for (int mt = 0; mt < 4; mt++) {
                    int row = wm * 64 + mt * 16 + row_off;
                    uint32_t addr = tb + (uint32_t)row * 128u
                                  + (uint32_t)((g ^ (row & 7)) << 4);
                    LDM4(ah[mt], addr);
                    LDM4(al[mt], addr + 16384u);
                }
            }
            // B fragments (hi & lo), 4 n-tiles via 2 x4 loads
            uint32_t bh[4][2], bl[4][2];
            {
                int grp = lane >> 3;
                #pragma unroll
                for (int p = 0; p < 2; p++) {
                    int tile = 2 * p + (grp >> 1);
                    int g = g0 + (grp & 1);
                    int nrow = wn * 32 + tile * 8 + (lane & 7);
                    uint32_t addr = tb + 32768u + (uint32_t)nrow * 128u
                                  + (uint32_t)((g ^ (nrow & 7)) << 4);
                    uint32_t r4[4];
                    LDM4(r4, addr);
                    bh[2*p][0] = r4[0]; bh[2*p][1] = r4[1];
                    bh[2*p+1][0] = r4[2]; bh[2*p+1][1] = r4[3];
                    LDM4(r4, addr + 16384u);
                    bl[2*p][0] = r4[0]; bl[2*p][1] = r4[1];
                    bl[2*p+1][0] = r4[2]; bl[2*p+1][1] = r4[3];
                }
            }
            #pragma unroll
            for (int mt = 0; mt < 4; mt++) {
                #pragma unroll
                for (int ntl = 0; ntl < 4; ntl++) {
                    MMA16816(acc[mt][ntl], ah[mt], bh[ntl]);
                    MMA16816(acc[mt][ntl], ah[mt], bl[ntl]);
                    MMA16816(acc[mt][ntl], al[mt], bh[ntl]);
                }
            }
        }
        __syncthreads();
    }

    // epilogue
    float s = 1.f, mu = 0.f, be = 0.f;
    if (EPI == EPI_COMB) { s = bn[0]*rsqrtf(bn[3]+1e-5f); mu = bn[2]; be = bn[1]; }
    #pragma unroll
    for (int mt = 0; mt < 4; mt++) {
        #pragma unroll
        for (int ntl = 0; ntl < 4; ntl++) {
            int row = m0 + wm*64 + mt*16 + (lane >> 2);
            int col = n0 + wn*32 + ntl*8 + (lane & 3)*2;
            if (EPI == EPI_C) {
                *(float2*)(Cf + (size_t)row*N + col) =
                    make_float2(acc[mt][ntl][0], acc[mt][ntl][1]);
                *(float2*)(Cf + (size_t)(row+8)*N + col) =
                    make_float2(acc[mt][ntl][2], acc[mt][ntl][3]);
            } else {
                #pragma unroll
                for (int q = 0; q < 4; q++) {
                    int r = row + (q >> 1)*8;
                    int c = col + (q & 1);
                    float v = acc[mt][ntl][q] + bias[c];
                    v = fmaxf((v - mu)*s + be, 0.f);
                    __nv_bfloat16 hv = __float2bfloat16(v);
                    Ohi[(size_t)r*HH + c] = hv;
                    Olo[(size_t)r*HH + c] = __float2bfloat16(v - __bfloat162float(hv));
                }
            }
        }
    }
}

// ---------------- weight split (one-shot) ------------------------------------
__global__ void split_w_kernel(const float* __restrict__ src,
                               __nv_bfloat16* __restrict__ hi, __nv_bfloat16* __restrict__ lo,
                               int rows, int K, int Kpad)
{
    int idx = blockIdx.x*blockDim.x + threadIdx.x;
    if (idx >= rows*Kpad) return;
    int r = idx / Kpad, k = idx - r*Kpad;
    float v = (k < K) ? src[(size_t)r*K + k] : 0.f;
    __nv_bfloat16 h = __float2bfloat16(v);
    hi[idx] = h;
    lo[idx] = __float2bfloat16(v - __bfloat162float(h));
}

// ---------------- small / fused kernels --------------------------------------
__global__ void init_kernel()
{
    int idx = blockIdx.x*blockDim.x + threadIdx.x;
    if (idx < BB*HH) {
        g_h[idx] = 0.f;
        g_h_hi[idx] = __float2bfloat16(0.f);
        g_h_lo[idx] = __float2bfloat16(0.f);
    }
    if (idx < BB) g_inp[idx] = TT;   // SOS = tagset_size
}

// encoder embedding lookup + max_norm=10 renorm -> split bf16 (padded to EEP)
__global__ void embed_renorm_kernel(const int* __restrict__ tokens,
                                    const float* __restrict__ w2v)
{
    int row = blockIdx.x;
    int tok = tokens[row];
    const float* src = w2v + (size_t)tok*EE;
    __shared__ float red[128];
    float ss = 0.f;
    for (int k = threadIdx.x; k < EE; k += blockDim.x) { float v = src[k]; ss += v*v; }
    red[threadIdx.x] = ss; __syncthreads();
    for (int s = blockDim.x>>1; s>0; s>>=1) {
        if (threadIdx.x < s) red[threadIdx.x] += red[threadIdx.x+s];
        __syncthreads();
    }
    float sc = fminf(1.f, 10.f/(sqrtf(red[0])+1e-7f));
    for (int k = threadIdx.x; k < EE; k += blockDim.x) {
        float v = src[k]*sc;
        __nv_bfloat16 h = __float2bfloat16(v);
        g_x_hi[(size_t)row*EEP + k] = h;
        g_x_lo[(size_t)row*EEP + k] = __float2bfloat16(v - __bfloat162float(h));
    }
    for (int k = EE + threadIdx.x; k < EEP; k += blockDim.x) {
        g_x_hi[(size_t)row*EEP + k] = __float2bfloat16(0.f);
        g_x_lo[(size_t)row*EEP + k] = __float2bfloat16(0.f);
    }
}

// GRU cell; writes h fp32 + split bf16 (and optional enc_out slot)
__global__ void gru_kernel(const float* __restrict__ gi0, int gi_stride,
                           const float* __restrict__ bih,
                           const float* __restrict__ gh0,
                           const float* __restrict__ bhh,
                           float* __restrict__ h,
                           float* __restrict__ outp, int out_stride)
{
    int idx = blockIdx.x*blockDim.x + threadIdx.x;
    if (idx >= BB*HH) return;
    int b = idx / HH, j = idx - b*HH;
    const float* p = gi0 + (size_t)b*gi_stride;
    float i_r = p[j], i_z = p[HH+j], i_n = p[2*HH+j];
    if (bih) { i_r += bih[j]; i_z += bih[HH+j]; i_n += bih[2*HH+j]; }
    const float* q = gh0 + (size_t)b*3*HH;
    float h_r = q[j]      + bhh[j];
    float h_z = q[HH+j]   + bhh[HH+j];
    float h_n = q[2*HH+j] + bhh[2*HH+j];
    float r = sigmoidf_(i_r + h_r);
    float z = sigmoidf_(i_z + h_z);
    float n = tanhf(i_n + r*h_n);
    float hn = (1.f - z)*n + z*h[idx];
    h[idx] = hn;
    __nv_bfloat16 hv = __float2bfloat16(hn);
    g_h_hi[idx] = hv;
    g_h_lo[idx] = __float2bfloat16(hn - __bfloat162float(hv));
    if (outp) outp[(size_t)b*out_stride + j] = hn;
}

// fused: decoder embedding (+renorm) -> attention -> softmax -> applied
__global__ __launch_bounds__(256) void dec_attn_kernel(
    const float* __restrict__ dec_emb,
    const float* __restrict__ attn_W, const float* __restrict__ attn_b)
{
    int b = blockIdx.x, tid = threadIdx.x;
    __shared__ float semb[DD];
    __shared__ float sh[HH];
    __shared__ float saw[32];
    __shared__ float red[256];

    int tok = g_inp[b];
    float val = dec_emb[(size_t)tok*DD + tid];
    red[tid] = val*val; __syncthreads();
    for (int s=128; s>0; s>>=1) { if (tid<s) red[tid]+=red[tid+s]; __syncthreads(); }
    float sc = fminf(1.f, 1.f/(sqrtf(red[0])+1e-7f));
    float e = val*sc;
    semb[tid] = e;
    {
        __nv_bfloat16 h = __float2bfloat16(e);
        g_cat_hi[(size_t)b*CATW + tid] = h;
        g_cat_lo[(size_t)b*CATW + tid] = __float2bfloat16(e - __bfloat162float(h));
    }
    for (int k = tid; k < HH; k += 256) sh[k] = g_h[(size_t)b*HH + k];
    __syncthreads();

    int warp = tid>>5, lane = tid&31;
    for (int l = warp; l < LL; l += 8) {
        const float* w = attn_W + (size_t)l*CATW;
        float acc = 0.f;
        for (int k = lane; k < DD; k += 32) acc += semb[k]*w[k];
        for (int k = lane; k < HH; k += 32) acc += sh[k]*w[DD+k];
        for (int o=16;o;o>>=1) acc += __shfl_xor_sync(0xffffffffu, acc, o);
        if (lane==0) saw[l] = acc + attn_b[l];
    }
    __syncthreads();
    if (warp==0) {
        float v = (lane<LL)? saw[lane] : -1e30f;
        float m = v;
        for (int o=16;o;o>>=1) m = fmaxf(m, __shfl_xor_sync(0xffffffffu, m, o));
        float ex = (lane<LL)? expf(v-m) : 0.f;
        float sm = ex;
        for (int o=16;o;o>>=1) sm += __shfl_xor_sync(0xffffffffu, sm, o);
        if (lane<LL) saw[lane] = ex/sm;
    }
    __syncthreads();

    const float* eo = g_enc_out + (size_t)b*LL*HH;
    for (int j = tid; j < HH; j += 256) {
        float acc = 0.f;
        #pragma unroll
        for (int l=0;l<LL;l++) acc += saw[l]*eo[(size_t)l*HH + j];
        __nv_bfloat16 h = __float2bfloat16(acc);
        g_cat_hi[(size_t)b*CATW + DD + j] = h;
        g_cat_lo[(size_t)b*CATW + DD + j] = __float2bfloat16(acc - __bfloat162float(h));
    }
}

// fused: bn1(h) @ out_W^T + out_b -> log_softmax -> argmax -> next input
__global__ __launch_bounds__(256) void out_lsm_kernel(
    const float* __restrict__ Wt, const float* __restrict__ ob,
    const float* __restrict__ bn, float* __restrict__ out, int t)
{
    constexpr int CH = 64;
    __shared__ float hsh[HH];
    __shared__ float Ws[TT][CH+1];
    __shared__ float red[256];
    __shared__ int   redi[128];

    int b = blockIdx.x, tid = threadIdx.x;
    int v = tid & 127, half = tid >> 7;
    float s = bn[0]*rsqrtf(bn[3]+1e-5f), mu = bn[2], beta = bn[1];
    for (int k = tid; k < HH; k += 256)
        hsh[k] = (g_h[(size_t)b*HH + k] - mu)*s + beta;

    float acc = 0.f;
    for (int k0 = 0; k0 < HH; k0 += CH) {
        __syncthreads();
        for (int i = tid; i < TT*CH; i += 256) {
            int r = i >> 6, c = i & 63;
            Ws[r][c] = Wt[(size_t)r*HH + k0 + c];
        }
        __syncthreads();
        const int kb = half*32;
        #pragma unroll
        for (int k = 0; k < 32; k++)
            acc += hsh[k0 + kb + k] * Ws[v][kb + k];
    }
    __syncthreads();
    red[tid] = acc; __syncthreads();
    float x = 0.f;
    if (tid < 128) x = red[tid] + red[tid+128] + ob[tid];
    __syncthreads();
    if (tid < 128) { red[tid] = x; redi[tid] = tid; }
    __syncthreads();
    for (int st = 64; st > 0; st >>= 1) {
        if (tid < st) {
            if (red[tid+st] > red[tid]) { red[tid]=red[tid+st]; redi[tid]=redi[tid+st]; }
        }
        __syncthreads();
    }
    float m = red[0]; int am = redi[0];
    __syncthreads();
    red[tid] = (tid < 128) ? expf(x - m) : 0.f;
    __syncthreads();
    for (int st = 128; st > 0; st >>= 1) { if (tid<st) red[tid]+=red[tid+st]; __syncthreads(); }
    float lse = logf(red[0]);
    if (tid < 128) out[((size_t)b*LL + t)*TT + tid] = x - m - lse;
    if (tid == 0) g_inp[b] = am;
}

// ---------------- launch ------------------------------------------------------
extern "C" void kernel_launch(void* const* d_in, const int* in_sizes, int n_in,
                              void* d_out, int out_size)
{
    const int*   tokens  = (const int*)  d_in[0];
    const float* w2v     = (const float*)d_in[1];
    const float* enc_Wih = (const float*)d_in[2];
    const float* enc_Whh = (const float*)d_in[3];
    const float* enc_bih = (const float*)d_in[4];
    const float* enc_bhh = (const float*)d_in[5];
    const float* dec_emb = (const float*)d_in[6];
    const float* attn_W  = (const float*)d_in[7];
    const float* attn_b  = (const float*)d_in[8];
    const float* comb_W  = (const float*)d_in[9];
    const float* comb_b  = (const float*)d_in[10];
    const float* dec_Wih = (const float*)d_in[11];
    const float* dec_Whh = (const float*)d_in[12];
    const float* dec_bih = (const float*)d_in[13];
    const float* dec_bhh = (const float*)d_in[14];
    const float* out_W   = (const float*)d_in[15];
    const float* out_b   = (const float*)d_in[16];
    const float* bn1     = (const float*)d_in[17];
    const float* bn2     = (const float*)d_in[18];
    float* out = (float*)d_out;

    __nv_bfloat16 *pxh, *pxl, *phh, *phl, *pch, *pcl, *poh, *pol;
    __nv_bfloat16 *pw_eih_h, *pw_eih_l, *pw_ehh_h, *pw_ehh_l;
    __nv_bfloat16 *pw_dih_h, *pw_dih_l, *pw_dhh_h, *pw_dhh_l, *pw_cmb_h, *pw_cmb_l;
    float *pgi_all, *penc_out, *ph, *pgh, *pgi_dec;
    cudaGetSymbolAddress((void**)&pxh, g_x_hi);       cudaGetSymbolAddress((void**)&pxl, g_x_lo);
    cudaGetSymbolAddress((void**)&phh, g_h_hi);       cudaGetSymbolAddress((void**)&phl, g_h_lo);
    cudaGetSymbolAddress((void**)&pch, g_cat_hi);     cudaGetSymbolAddress((void**)&pcl, g_cat_lo);
    cudaGetSymbolAddress((void**)&poh, g_o_hi);       cudaGetSymbolAddress((void**)&pol, g_o_lo);
    cudaGetSymbolAddress((void**)&pw_eih_h, g_wencih_hi); cudaGetSymbolAddress((void**)&pw_eih_l, g_wencih_lo);
    cudaGetSymbolAddress((void**)&pw_ehh_h, g_wenchh_hi); cudaGetSymbolAddress((void**)&pw_ehh_l, g_wenchh_lo);
    cudaGetSymbolAddress((void**)&pw_dih_h, g_wdecih_hi); cudaGetSymbolAddress((void**)&pw_dih_l, g_wdecih_lo);
    cudaGetSymbolAddress((void**)&pw_dhh_h, g_wdechh_hi); cudaGetSymbolAddress((void**)&pw_dhh_l, g_wdechh_lo);
    cudaGetSymbolAddress((void**)&pw_cmb_h, g_wcomb_hi);  cudaGetSymbolAddress((void**)&pw_cmb_l, g_wcomb_lo);
    cudaGetSymbolAddress((void**)&pgi_all,  g_gi_all);
    cudaGetSymbolAddress((void**)&penc_out, g_enc_out);
    cudaGetSymbolAddress((void**)&ph,       g_h);
    cudaGetSymbolAddress((void**)&pgh,      g_gh);
    cudaGetSymbolAddress((void**)&pgi_dec,  g_gi_dec);

    const int SMEM_MMA = 2 * 4 * 16384;   // 128 KB: double-buffered 4 tiles
    cudaFuncSetAttribute(mma_gemm<EPI_C>,    cudaFuncAttributeMaxDynamicSharedMemorySize, SMEM_MMA);
    cudaFuncSetAttribute(mma_gemm<EPI_COMB>, cudaFuncAttributeMaxDynamicSharedMemorySize, SMEM_MMA);

    const int EW = 2048;

    init_kernel<<<EW, 256>>>();

    // one-shot weight splits
    split_w_kernel<<<(3*HH*EEP + 255)/256, 256>>>(enc_Wih, pw_eih_h, pw_eih_l, 3*HH, EE, EEP);
    split_w_kernel<<<(3*HH*HH  + 255)/256, 256>>>(enc_Whh, pw_ehh_h, pw_ehh_l, 3*HH, HH, HH);
    split_w_kernel<<<(3*HH*HH  + 255)/256, 256>>>(dec_Wih, pw_dih_h, pw_dih_l, 3*HH, HH, HH);
    split_w_kernel<<<(3*HH*HH  + 255)/256, 256>>>(dec_Whh, pw_dhh_h, pw_dhh_l, 3*HH, HH, HH);
    split_w_kernel<<<(HH*CATW  + 255)/256, 256>>>(comb_W,  pw_cmb_h, pw_cmb_l, HH, CATW, CATW);

    // encoder embeddings + one-shot input-gate GEMM (bias added in gru)
    embed_renorm_kernel<<<BL, 128>>>(tokens, w2v);
    mma_gemm<EPI_C><<<dim3(3*HH/128, BL/128), 256, SMEM_MMA>>>(
        pxh, pxl, EEP, pw_eih_h, pw_eih_l, EEP, EEP,
        pgi_all, 3*HH, nullptr, nullptr, nullptr, nullptr);

    // encoder recurrence
    for (int t = 0; t < LL; t++) {
        mma_gemm<EPI_C><<<dim3(3*HH/128, BB/128), 256, SMEM_MMA>>>(
            phh, phl, HH, pw_ehh_h, pw_ehh_l, HH, HH,
            pgh, 3*HH, nullptr, nullptr, nullptr, nullptr);
        gru_kernel<<<EW, 256>>>(pgi_all + (size_t)t*3*HH, LL*3*HH, enc_bih,
                                pgh, enc_bhh, ph, penc_out + (size_t)t*HH, LL*HH);
    }

    // greedy attention decoder
    for (int t = 0; t < LL; t++) {
        dec_attn_kernel<<<BB, 256>>>(dec_emb, attn_W, attn_b);
        // comb: relu(bn2(cat @ comb_W^T + comb_b)) -> split o
        mma_gemm<EPI_COMB><<<dim3(HH/128, BB/128), 256, SMEM_MMA>>>(
            pch, pcl, CATW, pw_cmb_h, pw_cmb_l, CATW, CATW,
            nullptr, HH, comb_b, bn2, poh, pol);
        // gi = o @ dec_Wih^T  (bias added in gru)
        mma_gemm<EPI_C><<<dim3(3*HH/128, BB/128), 256, SMEM_MMA>>>(
            poh, pol, HH, pw_dih_h, pw_dih_l, HH, HH,
            pgi_dec, 3*HH, nullptr, nullptr, nullptr, nullptr);
        // gh = h @ dec_Whh^T
        mma_gemm<EPI_C><<<dim3(3*HH/128, BB/128), 256, SMEM_MMA>>>(
            phh, phl, HH, pw_dhh_h, pw_dhh_l, HH, HH,
            pgh, 3*HH, nullptr, nullptr, nullptr, nullptr);
        gru_kernel<<<EW, 256>>>(pgi_dec, 3*HH, dec_bih, pgh, dec_bhh, ph, nullptr, 0);
        out_lsm_kernel<<<BB, 256>>>(out_W, out_b, bn1, out, t);
    }
}

// round 7
// speedup vs baseline: 1.8314x; 1.2005x over previous
#include <cuda_runtime.h>
#include <cuda_bf16.h>
#include <math.h>
#include <stdint.h>

// Problem constants
#define BB 512
#define LL 25
#define EE 300
#define EEP 320
#define HH 1024
#define DD 256
#define TT 128
#define BL (BB*LL)       // 12800
#define CATW (DD+HH)     // 1280

// ---------------- scratch (device globals; no allocation allowed) -----------
__device__ __nv_bfloat16 g_x_hi[BL*EEP], g_x_lo[BL*EEP];
__device__ float g_gi_all[BL*3*HH];
__device__ float g_enc_out[BL*HH];
__device__ float g_h[BB*HH];
__device__ __nv_bfloat16 g_h_hi[BB*HH], g_h_lo[BB*HH];
__device__ float g_gh[BB*3*HH];
__device__ __nv_bfloat16 g_cat_hi[BB*CATW], g_cat_lo[BB*CATW];
__device__ __nv_bfloat16 g_o_hi[BB*HH], g_o_lo[BB*HH];
__device__ float g_gi_dec[BB*3*HH];
__device__ int   g_inp[BB];
__device__ __nv_bfloat16 g_wencih_hi[3*HH*EEP], g_wencih_lo[3*HH*EEP];
__device__ __nv_bfloat16 g_wenchh_hi[3*HH*HH],  g_wenchh_lo[3*HH*HH];
__device__ __nv_bfloat16 g_wdecih_hi[3*HH*HH],  g_wdecih_lo[3*HH*HH];
__device__ __nv_bfloat16 g_wdechh_hi[3*HH*HH],  g_wdechh_lo[3*HH*HH];
__device__ __nv_bfloat16 g_wcomb_hi[HH*CATW],   g_wcomb_lo[HH*CATW];

__device__ __forceinline__ float sigmoidf_(float x) { return 1.f/(1.f+expf(-x)); }

__device__ __forceinline__ uint32_t smem_u32(const void* p) {
    uint32_t a;
    asm("{ .reg .u64 t; cvta.to.shared.u64 t, %1; cvt.u32.u64 %0, t; }" : "=r"(a) : "l"(p));
    return a;
}

#define LDM4(r, addr) \
    asm volatile("ldmatrix.sync.aligned.m8n8.x4.shared.b16 {%0,%1,%2,%3}, [%4];" \
        : "=r"((r)[0]), "=r"((r)[1]), "=r"((r)[2]), "=r"((r)[3]) : "r"(addr))

#define MMA16816(d, a, b) \
    asm volatile("mma.sync.aligned.m16n8k16.row.col.f32.bf16.bf16.f32 " \
        "{%0,%1,%2,%3}, {%4,%5,%6,%7}, {%8,%9}, {%0,%1,%2,%3};" \
        : "+f"((d)[0]), "+f"((d)[1]), "+f"((d)[2]), "+f"((d)[3]) \
        : "r"((a)[0]), "r"((a)[1]), "r"((a)[2]), "r"((a)[3]), "r"((b)[0]), "r"((b)[1]))

#define CPASYNC16(dst, src) \
    asm volatile("cp.async.cg.shared.global [%0], [%1], 16;" :: "r"(dst), "l"(src))

// ---------------- HMMA bf16 3-term split GEMM body ---------------------------
// C(M,N) = A(M,K)*B(N,K)^T, CTA 128x128, BK=64, 256 threads.
enum { EPI_C=0, EPI_COMB=1 };

template<int EPI>
__device__ __forceinline__ void mma_body(
    char* sm, int bx, int by,
    const __nv_bfloat16* __restrict__ Ahi, const __nv_bfloat16* __restrict__ Alo, int lda,
    const __nv_bfloat16* __restrict__ Bhi, const __nv_bfloat16* __restrict__ Blo, int ldb,
    int K, float* __restrict__ Cf, int N,
    const float* __restrict__ bias, const float* __restrict__ bn,
    __nv_bfloat16* __restrict__ Ohi, __nv_bfloat16* __restrict__ Olo)
{
    const int tid  = threadIdx.x;
    const int lane = tid & 31, wid = tid >> 5;
    const int wm   = wid & 1;
    const int wn   = wid >> 1;
    const int m0   = by * 128, n0 = bx * 128;
    const uint32_t sbase = smem_u32(sm);

    const int sr = tid >> 1, sh = tid & 1;
    const __nv_bfloat16* tsrc[4];
    tsrc[0] = Ahi + (size_t)(m0 + sr) * lda;
    tsrc[1] = Alo + (size_t)(m0 + sr) * lda;
    tsrc[2] = Bhi + (size_t)(n0 + sr) * ldb;
    tsrc[3] = Blo + (size_t)(n0 + sr) * ldb;
    const uint32_t swrow = (uint32_t)(sr & 7);

    auto stage = [&](int buf, int k0) {
        uint32_t dbase = sbase + (uint32_t)buf * 65536u + (uint32_t)sr * 128u;
        #pragma unroll
        for (int t = 0; t < 4; t++) {
            const __nv_bfloat16* s = tsrc[t] + k0 + sh * 32;
            uint32_t db = dbase + (uint32_t)t * 16384u;
            #pragma unroll
            for (int c = 0; c < 4; c++) {
                uint32_t g = (uint32_t)(sh * 4 + c);
                uint32_t dst = db + ((g ^ swrow) << 4);
                CPASYNC16(dst, s + c * 8);
            }
        }
        asm volatile("cp.async.commit_group;" ::: "memory");
    };

    float acc[4][4][4];
    #pragma unroll
    for (int i = 0; i < 4; i++)
        #pragma unroll
        for (int j = 0; j < 4; j++)
            #pragma unroll
            for (int q = 0; q < 4; q++) acc[i][j][q] = 0.f;

    const int nt = K / 64;
    stage(0, 0);
    for (int it = 0; it < nt; it++) {
        if (it + 1 < nt) {
            stage((it + 1) & 1, (it + 1) * 64);
            asm volatile("cp.async.wait_group 1;" ::: "memory");
        } else {
            asm volatile("cp.async.wait_group 0;" ::: "memory");
        }
        __syncthreads();

        uint32_t tb = sbase + (uint32_t)(it & 1) * 65536u;
        #pragma unroll
        for (int ks = 0; ks < 4; ks++) {
            const int g0 = ks * 2;
            uint32_t ah[4][4], al[4][4];
            {
                int row_off = ((lane >> 3) & 1) * 8 + (lane & 7);
                int g = g0 + (lane >> 4);
                #pragma unroll
                for (int mt = 0; mt < 4; mt++) {
                    int row = wm * 64 + mt * 16 + row_off;
                    uint32_t addr = tb + (uint32_t)row * 128u
                                  + (uint32_t)((g ^ (row & 7)) << 4);
                    LDM4(ah[mt], addr);
                    LDM4(al[mt], addr + 16384u);
                }
            }
            uint32_t bh[4][2], bl[4][2];
            {
                int grp = lane >> 3;
                #pragma unroll
                for (int p = 0; p < 2; p++) {
                    int tile = 2 * p + (grp >> 1);
                    int g = g0 + (grp & 1);
                    int nrow = wn * 32 + tile * 8 + (lane & 7);
                    uint32_t addr = tb + 32768u + (uint32_t)nrow * 128u
                                  + (uint32_t)((g ^ (nrow & 7)) << 4);
                    uint32_t r4[4];
                    LDM4(r4, addr);
                    bh[2*p][0] = r4[0]; bh[2*p][1] = r4[1];
                    bh[2*p+1][0] = r4[2]; bh[2*p+1][1] = r4[3];
                    LDM4(r4, addr + 16384u);
                    bl[2*p][0] = r4[0]; bl[2*p][1] = r4[1];
                    bl[2*p+1][0] = r4[2]; bl[2*p+1][1] = r4[3];
                }
            }
            #pragma unroll
            for (int mt = 0; mt < 4; mt++) {
                #pragma unroll
                for (int ntl = 0; ntl < 4; ntl++) {
                    MMA16816(acc[mt][ntl], ah[mt], bh[ntl]);
                    MMA16816(acc[mt][ntl], ah[mt], bl[ntl]);
                    MMA16816(acc[mt][ntl], al[mt], bh[ntl]);
                }
            }
        }
        __syncthreads();
    }

    float s = 1.f, mu = 0.f, be = 0.f;
    if (EPI == EPI_COMB) { s = bn[0]*rsqrtf(bn[3]+1e-5f); mu = bn[2]; be = bn[1]; }
    #pragma unroll
    for (int mt = 0; mt < 4; mt++) {
        #pragma unroll
        for (int ntl = 0; ntl < 4; ntl++) {
            int row = m0 + wm*64 + mt*16 + (lane >> 2);
            int col = n0 + wn*32 + ntl*8 + (lane & 3)*2;
            if (EPI == EPI_C) {
                *(float2*)(Cf + (size_t)row*N + col) =
                    make_float2(acc[mt][ntl][0], acc[mt][ntl][1]);
                *(float2*)(Cf + (size_t)(row+8)*N + col) =
                    make_float2(acc[mt][ntl][2], acc[mt][ntl][3]);
            } else {
                #pragma unroll
                for (int q = 0; q < 4; q++) {
                    int r = row + (q >> 1)*8;
                    int c = col + (q & 1);
                    float v = acc[mt][ntl][q] + bias[c];
                    v = fmaxf((v - mu)*s + be, 0.f);
                    __nv_bfloat16 hv = __float2bfloat16(v);
                    Ohi[(size_t)r*HH + c] = hv;
                    Olo[(size_t)r*HH + c] = __float2bfloat16(v - __bfloat162float(hv));
                }
            }
        }
    }
}

__global__ __launch_bounds__(256) void mma_gemm(
    const __nv_bfloat16* __restrict__ Ahi, const __nv_bfloat16* __restrict__ Alo, int lda,
    const __nv_bfloat16* __restrict__ Bhi, const __nv_bfloat16* __restrict__ Blo, int ldb,
    int K, float* __restrict__ Cf, int N)
{
    extern __shared__ char sm[];
    mma_body<EPI_C>(sm, blockIdx.x, blockIdx.y, Ahi, Alo, lda, Bhi, Blo, ldb,
                    K, Cf, N, nullptr, nullptr, nullptr, nullptr);
}

// merged decoder launch: z=0 -> gh = h @ dec_Whh^T (24x4 blocks);
//                        z=1 -> comb (only x<8 active): relu(bn2(cat@combW^T+cb)) -> split o
__global__ __launch_bounds__(256) void comb_gh_kernel(
    const __nv_bfloat16* __restrict__ hhi, const __nv_bfloat16* __restrict__ hlo,
    const __nv_bfloat16* __restrict__ whh_hi, const __nv_bfloat16* __restrict__ whh_lo,
    float* __restrict__ gh,
    const __nv_bfloat16* __restrict__ chi, const __nv_bfloat16* __restrict__ clo,
    const __nv_bfloat16* __restrict__ wc_hi, const __nv_bfloat16* __restrict__ wc_lo,
    const float* __restrict__ comb_b, const float* __restrict__ bn2,
    __nv_bfloat16* __restrict__ ohi, __nv_bfloat16* __restrict__ olo)
{
    extern __shared__ char sm[];
    if (blockIdx.z == 0) {
        mma_body<EPI_C>(sm, blockIdx.x, blockIdx.y, hhi, hlo, HH, whh_hi, whh_lo, HH,
                        HH, gh, 3*HH, nullptr, nullptr, nullptr, nullptr);
    } else {
        if (blockIdx.x >= HH/128) return;
        mma_body<EPI_COMB>(sm, blockIdx.x, blockIdx.y, chi, clo, CATW, wc_hi, wc_lo, CATW,
                           CATW, nullptr, HH, comb_b, bn2, ohi, olo);
    }
}

// ---------------- weight splits (2 launches for profile alignment) -----------
__device__ __forceinline__ void split_seg(const float* src, __nv_bfloat16* hi,
                                          __nv_bfloat16* lo, int idx, int K, int Kpad)
{
    int r = idx / Kpad, k = idx - r*Kpad;
    float v = (k < K) ? src[(size_t)r*K + k] : 0.f;
    __nv_bfloat16 h = __float2bfloat16(v);
    hi[idx] = h;
    lo[idx] = __float2bfloat16(v - __bfloat162float(h));
}

__global__ void split_a_kernel(const float* __restrict__ w_eih, const float* __restrict__ w_ehh)
{
    int idx = blockIdx.x*blockDim.x + threadIdx.x;
    const int n0 = 3*HH*EEP, n1 = 3*HH*HH;
    if (idx < n0) split_seg(w_eih, g_wencih_hi, g_wencih_lo, idx, EE, EEP);
    else if (idx < n0 + n1) split_seg(w_ehh, g_wenchh_hi, g_wenchh_lo, idx - n0, HH, HH);
}

__global__ void split_b_kernel(const float* __restrict__ w_dih, const float* __restrict__ w_dhh,
                               const float* __restrict__ w_cmb)
{
    int idx = blockIdx.x*blockDim.x + threadIdx.x;
    const int n0 = 3*HH*HH, n1 = 3*HH*HH, n2 = HH*CATW;
    if (idx < n0) split_seg(w_dih, g_wdecih_hi, g_wdecih_lo, idx, HH, HH);
    else if (idx < n0+n1) split_seg(w_dhh, g_wdechh_hi, g_wdechh_lo, idx - n0, HH, HH);
    else if (idx < n0+n1+n2) split_seg(w_cmb, g_wcomb_hi, g_wcomb_lo, idx - n0 - n1, CATW, CATW);
}

// ---------------- small / fused kernels --------------------------------------
__global__ void init_kernel()
{
    int idx = blockIdx.x*blockDim.x + threadIdx.x;
    if (idx < BB*HH) {
        g_h[idx] = 0.f;
        g_h_hi[idx] = __float2bfloat16(0.f);
        g_h_lo[idx] = __float2bfloat16(0.f);
    }
    if (idx < BB) g_inp[idx] = TT;
}

__global__ void embed_renorm_kernel(const int* __restrict__ tokens,
                                    const float* __restrict__ w2v)
{
    int row = blockIdx.x;
    int tok = tokens[row];
    const float* src = w2v + (size_t)tok*EE;
    __shared__ float red[128];
    float ss = 0.f;
    for (int k = threadIdx.x; k < EE; k += blockDim.x) { float v = src[k]; ss += v*v; }
    red[threadIdx.x] = ss; __syncthreads();
    for (int s = blockDim.x>>1; s>0; s>>=1) {
        if (threadIdx.x < s) red[threadIdx.x] += red[threadIdx.x+s];
        __syncthreads();
    }
    float sc = fminf(1.f, 10.f/(sqrtf(red[0])+1e-7f));
    for (int k = threadIdx.x; k < EE; k += blockDim.x) {
        float v = src[k]*sc;
        __nv_bfloat16 h = __float2bfloat16(v);
        g_x_hi[(size_t)row*EEP + k] = h;
        g_x_lo[(size_t)row*EEP + k] = __float2bfloat16(v - __bfloat162float(h));
    }
    for (int k = EE + threadIdx.x; k < EEP; k += blockDim.x) {
        g_x_hi[(size_t)row*EEP + k] = __float2bfloat16(0.f);
        g_x_lo[(size_t)row*EEP + k] = __float2bfloat16(0.f);
    }
}

__global__ void gru_kernel(const float* __restrict__ gi0, int gi_stride,
                           const float* __restrict__ bih,
                           const float* __restrict__ gh0,
                           const float* __restrict__ bhh,
                           float* __restrict__ h,
                           float* __restrict__ outp, int out_stride)
{
    int idx = blockIdx.x*blockDim.x + threadIdx.x;
    if (idx >= BB*HH) return;
    int b = idx / HH, j = idx - b*HH;
    const float* p = gi0 + (size_t)b*gi_stride;
    float i_r = p[j], i_z = p[HH+j], i_n = p[2*HH+j];
    if (bih) { i_r += bih[j]; i_z += bih[HH+j]; i_n += bih[2*HH+j]; }
    const float* q = gh0 + (size_t)b*3*HH;
    float h_r = q[j]      + bhh[j];
    float h_z = q[HH+j]   + bhh[HH+j];
    float h_n = q[2*HH+j] + bhh[2*HH+j];
    float r = sigmoidf_(i_r + h_r);
    float z = sigmoidf_(i_z + h_z);
    float n = tanhf(i_n + r*h_n);
    float hn = (1.f - z)*n + z*h[idx];
    h[idx] = hn;
    __nv_bfloat16 hv = __float2bfloat16(hn);
    g_h_hi[idx] = hv;
    g_h_lo[idx] = __float2bfloat16(hn - __bfloat162float(hv));
    if (outp) outp[(size_t)b*out_stride + j] = hn;
}

// merged: [log_softmax+argmax of step lsm_t] then [embedding+attn+applied for next step]
__global__ __launch_bounds__(256) void lsm_attn_kernel(
    const float* __restrict__ dec_emb,
    const float* __restrict__ attn_W, const float* __restrict__ attn_b,
    const float* __restrict__ Wt, const float* __restrict__ ob,
    const float* __restrict__ bn, float* __restrict__ out,
    int lsm_t, int do_attn)
{
    constexpr int CH = 64;
    __shared__ float sh[HH];          // raw h
    __shared__ float Ws[TT][CH+1];
    __shared__ float red[256];
    __shared__ int   redi[128];
    __shared__ float semb[DD];
    __shared__ float saw[32];

    int b = blockIdx.x, tid = threadIdx.x;
    for (int k = tid; k < HH; k += 256) sh[k] = g_h[(size_t)b*HH + k];
    __syncthreads();

    int token;
    if (lsm_t >= 0) {
        int v = tid & 127, half = tid >> 7;
        float s = bn[0]*rsqrtf(bn[3]+1e-5f);
        float c0 = bn[1] - bn[2]*s;
        float acc = 0.f;
        for (int k0 = 0; k0 < HH; k0 += CH) {
            __syncthreads();
            for (int i = tid; i < TT*CH; i += 256) {
                int r = i >> 6, c = i & 63;
                Ws[r][c] = Wt[(size_t)r*HH + k0 + c];
            }
            __syncthreads();
            const int kb = half*32;
            #pragma unroll
            for (int k = 0; k < 32; k++)
                acc += (sh[k0 + kb + k]*s + c0) * Ws[v][kb + k];
        }
        __syncthreads();
        red[tid] = acc; __syncthreads();
        float x = 0.f;
        if (tid < 128) x = red[tid] + red[tid+128] + ob[tid];
        __syncthreads();
        if (tid < 128) { red[tid] = x; redi[tid] = tid; }
        __syncthreads();
        for (int st = 64; st > 0; st >>= 1) {
            if (tid < st) {
                if (red[tid+st] > red[tid]) { red[tid]=red[tid+st]; redi[tid]=redi[tid+st]; }
            }
            __syncthreads();
        }
        float m = red[0]; int am = redi[0];
        __syncthreads();
        red[tid] = (tid < 128) ? expf(x - m) : 0.f;
        __syncthreads();
        for (int st = 128; st > 0; st >>= 1) { if (tid<st) red[tid]+=red[tid+st]; __syncthreads(); }
        float lse = logf(red[0]);
        if (tid < 128) out[((size_t)b*LL + lsm_t)*TT + tid] = x - m - lse;
        token = am;
        __syncthreads();
    } else {
        token = g_inp[b];   // SOS
    }

    if (!do_attn) return;

    // embedding + renorm
    float val = dec_emb[(size_t)token*DD + tid];   // tid < 256 == DD
    red[tid] = val*val; __syncthreads();
    for (int s=128; s>0; s>>=1) { if (tid<s) red[tid]+=red[tid+s]; __syncthreads(); }
    float sc = fminf(1.f, 1.f/(sqrtf(red[0])+1e-7f));
    float e = val*sc;
    semb[tid] = e;
    {
        __nv_bfloat16 h = __float2bfloat16(e);
        g_cat_hi[(size_t)b*CATW + tid] = h;
        g_cat_lo[(size_t)b*CATW + tid] = __float2bfloat16(e - __bfloat162float(h));
    }
    __syncthreads();

    int warp = tid>>5, lane = tid&31;
    for (int l = warp; l < LL; l += 8) {
        const float* w = attn_W + (size_t)l*CATW;
        float acc = 0.f;
        for (int k = lane; k < DD; k += 32) acc += semb[k]*w[k];
        for (int k = lane; k < HH; k += 32) acc += sh[k]*w[DD+k];
        for (int o=16;o;o>>=1) acc += __shfl_xor_sync(0xffffffffu, acc, o);
        if (lane==0) saw[l] = acc + attn_b[l];
    }
    __syncthreads();
    if (warp==0) {
        float v = (lane<LL)? saw[lane] : -1e30f;
        float m = v;
        for (int o=16;o;o>>=1) m = fmaxf(m, __shfl_xor_sync(0xffffffffu, m, o));
        float ex = (lane<LL)? expf(v-m) : 0.f;
        float sm = ex;
        for (int o=16;o;o>>=1) sm += __shfl_xor_sync(0xffffffffu, sm, o);
        if (lane<LL) saw[lane] = ex/sm;
    }
    __syncthreads();

    const float* eo = g_enc_out + (size_t)b*LL*HH;
    for (int j = tid; j < HH; j += 256) {
        float acc = 0.f;
        #pragma unroll
        for (int l=0;l<LL;l++) acc += saw[l]*eo[(size_t)l*HH + j];
        __nv_bfloat16 h = __float2bfloat16(acc);
        g_cat_hi[(size_t)b*CATW + DD + j] = h;
        g_cat_lo[(size_t)b*CATW + DD + j] = __float2bfloat16(acc - __bfloat162float(h));
    }
}

// ---------------- launch ------------------------------------------------------
extern "C" void kernel_launch(void* const* d_in, const int* in_sizes, int n_in,
                              void* d_out, int out_size)
{
    const int*   tokens  = (const int*)  d_in[0];
    const float* w2v     = (const float*)d_in[1];
    const float* enc_Wih = (const float*)d_in[2];
    const float* enc_Whh = (const float*)d_in[3];
    const float* enc_bih = (const float*)d_in[4];
    const float* enc_bhh = (const float*)d_in[5];
    const float* dec_emb = (const float*)d_in[6];
    const float* attn_W  = (const float*)d_in[7];
    const float* attn_b  = (const float*)d_in[8];
    const float* comb_W  = (const float*)d_in[9];
    const float* comb_b  = (const float*)d_in[10];
    const float* dec_Wih = (const float*)d_in[11];
    const float* dec_Whh = (const float*)d_in[12];
    const float* dec_bih = (const float*)d_in[13];
    const float* dec_bhh = (const float*)d_in[14];
    const float* out_W   = (const float*)d_in[15];
    const float* out_b   = (const float*)d_in[16];
    const float* bn1     = (const float*)d_in[17];
    const float* bn2     = (const float*)d_in[18];
    float* out = (float*)d_out;

    __nv_bfloat16 *pxh, *pxl, *phh, *phl, *pch, *pcl, *poh, *pol;
    __nv_bfloat16 *pw_eih_h, *pw_eih_l, *pw_ehh_h, *pw_ehh_l;
    __nv_bfloat16 *pw_dih_h, *pw_dih_l, *pw_dhh_h, *pw_dhh_l, *pw_cmb_h, *pw_cmb_l;
    float *pgi_all, *penc_out, *ph, *pgh, *pgi_dec;
    cudaGetSymbolAddress((void**)&pxh, g_x_hi);       cudaGetSymbolAddress((void**)&pxl, g_x_lo);
    cudaGetSymbolAddress((void**)&phh, g_h_hi);       cudaGetSymbolAddress((void**)&phl, g_h_lo);
    cudaGetSymbolAddress((void**)&pch, g_cat_hi);     cudaGetSymbolAddress((void**)&pcl, g_cat_lo);
    cudaGetSymbolAddress((void**)&poh, g_o_hi);       cudaGetSymbolAddress((void**)&pol, g_o_lo);
    cudaGetSymbolAddress((void**)&pw_eih_h, g_wencih_hi); cudaGetSymbolAddress((void**)&pw_eih_l, g_wencih_lo);
    cudaGetSymbolAddress((void**)&pw_ehh_h, g_wenchh_hi); cudaGetSymbolAddress((void**)&pw_ehh_l, g_wenchh_lo);
    cudaGetSymbolAddress((void**)&pw_dih_h, g_wdecih_hi); cudaGetSymbolAddress((void**)&pw_dih_l, g_wdecih_lo);
    cudaGetSymbolAddress((void**)&pw_dhh_h, g_wdechh_hi); cudaGetSymbolAddress((void**)&pw_dhh_l, g_wdechh_lo);
    cudaGetSymbolAddress((void**)&pw_cmb_h, g_wcomb_hi);  cudaGetSymbolAddress((void**)&pw_cmb_l, g_wcomb_lo);
    cudaGetSymbolAddress((void**)&pgi_all,  g_gi_all);
    cudaGetSymbolAddress((void**)&penc_out, g_enc_out);
    cudaGetSymbolAddress((void**)&ph,       g_h);
    cudaGetSymbolAddress((void**)&pgh,      g_gh);
    cudaGetSymbolAddress((void**)&pgi_dec,  g_gi_dec);

    const int SMEM_MMA = 2 * 4 * 16384;   // 128 KB
    cudaFuncSetAttribute(mma_gemm,       cudaFuncAttributeMaxDynamicSharedMemorySize, SMEM_MMA);
    cudaFuncSetAttribute(comb_gh_kernel, cudaFuncAttributeMaxDynamicSharedMemorySize, SMEM_MMA);

    const int EW = 2048;

    // stream order: 0 init, 1 splitA, 2 splitB, 3 embed, 4 gi-gemm, 5 enc-gemm (ncu -s 5 target)
    init_kernel<<<EW, 256>>>();
    split_a_kernel<<<(3*HH*EEP + 3*HH*HH + 255)/256, 256>>>(enc_Wih, enc_Whh);
    split_b_kernel<<<(2*3*HH*HH + HH*CATW + 255)/256, 256>>>(dec_Wih, dec_Whh, comb_W);
    embed_renorm_kernel<<<BL, 128>>>(tokens, w2v);
    mma_gemm<<<dim3(3*HH/128, BL/128), 256, SMEM_MMA>>>(
        pxh, pxl, EEP, pw_eih_h, pw_eih_l, EEP, EEP, pgi_all, 3*HH);

    // encoder recurrence
    for (int t = 0; t < LL; t++) {
        mma_gemm<<<dim3(3*HH/128, BB/128), 256, SMEM_MMA>>>(
            phh, phl, HH, pw_ehh_h, pw_ehh_l, HH, HH, pgh, 3*HH);
        gru_kernel<<<EW, 256>>>(pgi_all + (size_t)t*3*HH, LL*3*HH, enc_bih,
                                pgh, enc_bhh, ph, penc_out + (size_t)t*HH, LL*HH);
    }

    // greedy attention decoder
    lsm_attn_kernel<<<BB, 256>>>(dec_emb, attn_W, attn_b, out_W, out_b, bn1, out, -1, 1);
    for (int t = 0; t < LL; t++) {
        comb_gh_kernel<<<dim3(3*HH/128, BB/128, 2), 256, SMEM_MMA>>>(
            phh, phl, pw_dhh_h, pw_dhh_l, pgh,
            pch, pcl, pw_cmb_h, pw_cmb_l, comb_b, bn2, poh, pol);
        mma_gemm<<<dim3(3*HH/128, BB/128), 256, SMEM_MMA>>>(
            poh, pol, HH, pw_dih_h, pw_dih_l, HH, HH, pgi_dec, 3*HH);
        gru_kernel<<<EW, 256>>>(pgi_dec, 3*HH, dec_bih, pgh, dec_bhh, ph, nullptr, 0);
        lsm_attn_kernel<<<BB, 256>>>(dec_emb, attn_W, attn_b, out_W, out_b, bn1, out,
                                     t, (t < LL-1) ? 1 : 0);
    }
}

// round 8
// speedup vs baseline: 1.9903x; 1.0868x over previous
#include <cuda_runtime.h>
#include <cuda_bf16.h>
#include <math.h>
#include <stdint.h>

// Problem constants
#define BB 512
#define LL 25
#define EE 300
#define EEP 320
#define HH 1024
#define DD 256
#define TT 128
#define BL (BB*LL)       // 12800
#define CATW (DD+HH)     // 1280

// ---------------- scratch (device globals; no allocation allowed) -----------
__device__ __nv_bfloat16 g_x_hi[BL*EEP], g_x_lo[BL*EEP];
__device__ float g_gi_all[BL*3*HH];
__device__ float g_enc_out[BL*HH];
__device__ float g_h[BB*HH];
__device__ __nv_bfloat16 g_h_hi[BB*HH], g_h_lo[BB*HH];
__device__ float g_gh[BB*3*HH];
__device__ __nv_bfloat16 g_cat_hi[BB*CATW], g_cat_lo[BB*CATW];
__device__ __nv_bfloat16 g_o_hi[BB*HH], g_o_lo[BB*HH];
__device__ float g_gi_dec[BB*3*HH];
__device__ int   g_inp[BB];
__device__ __nv_bfloat16 g_wencih_hi[3*HH*EEP], g_wencih_lo[3*HH*EEP];
__device__ __nv_bfloat16 g_wenchh_hi[3*HH*HH],  g_wenchh_lo[3*HH*HH];
__device__ __nv_bfloat16 g_wdecih_hi[3*HH*HH],  g_wdecih_lo[3*HH*HH];
__device__ __nv_bfloat16 g_wdechh_hi[3*HH*HH],  g_wdechh_lo[3*HH*HH];
__device__ __nv_bfloat16 g_wcomb_hi[HH*CATW],   g_wcomb_lo[HH*CATW];

__device__ __forceinline__ float sigmoidf_(float x) { return 1.f/(1.f+expf(-x)); }

__device__ __forceinline__ uint32_t smem_u32(const void* p) {
    uint32_t a;
    asm("{ .reg .u64 t; cvta.to.shared.u64 t, %1; cvt.u32.u64 %0, t; }" : "=r"(a) : "l"(p));
    return a;
}

#define LDM4(r, addr) \
    asm volatile("ldmatrix.sync.aligned.m8n8.x4.shared.b16 {%0,%1,%2,%3}, [%4];" \
        : "=r"((r)[0]), "=r"((r)[1]), "=r"((r)[2]), "=r"((r)[3]) : "r"(addr))

#define MMA16816(d, a, b) \
    asm volatile("mma.sync.aligned.m16n8k16.row.col.f32.bf16.bf16.f32 " \
        "{%0,%1,%2,%3}, {%4,%5,%6,%7}, {%8,%9}, {%0,%1,%2,%3};" \
        : "+f"((d)[0]), "+f"((d)[1]), "+f"((d)[2]), "+f"((d)[3]) \
        : "r"((a)[0]), "r"((a)[1]), "r"((a)[2]), "r"((a)[3]), "r"((b)[0]), "r"((b)[1]))

#define CPASYNC16(dst, src) \
    asm volatile("cp.async.cg.shared.global [%0], [%1], 16;" :: "r"(dst), "l"(src))

// ---------------- HMMA bf16 3-term split GEMM body ---------------------------
// C(M,N) = A(M,K)*B(N,K)^T, CTA 128x128, BK=64, 512 threads (16 warps, 32x32 each).
enum { EPI_C=0, EPI_COMB=1 };

template<int EPI>
__device__ __forceinline__ void mma_body(
    char* sm, int bx, int by,
    const __nv_bfloat16* __restrict__ Ahi, const __nv_bfloat16* __restrict__ Alo, int lda,
    const __nv_bfloat16* __restrict__ Bhi, const __nv_bfloat16* __restrict__ Blo, int ldb,
    int K, float* __restrict__ Cf, int N,
    const float* __restrict__ bias, const float* __restrict__ bn,
    __nv_bfloat16* __restrict__ Ohi, __nv_bfloat16* __restrict__ Olo)
{
    const int tid  = threadIdx.x;
    const int lane = tid & 31, wid = tid >> 5;
    const int wm   = wid & 3;          // 4 warp-rows of 32
    const int wn   = wid >> 2;         // 4 warp-cols of 32
    const int m0   = by * 128, n0 = bx * 128;
    const uint32_t sbase = smem_u32(sm);

    // staging: thread -> row sr (0..127), quarter sq (granule pair sq*2, sq*2+1)
    const int sr = tid >> 2, sq = tid & 3;
    const __nv_bfloat16* tsrc[4];
    tsrc[0] = Ahi + (size_t)(m0 + sr) * lda;
    tsrc[1] = Alo + (size_t)(m0 + sr) * lda;
    tsrc[2] = Bhi + (size_t)(n0 + sr) * ldb;
    tsrc[3] = Blo + (size_t)(n0 + sr) * ldb;
    const uint32_t swrow = (uint32_t)(sr & 7);

    auto stage = [&](int buf, int k0) {
        uint32_t dbase = sbase + (uint32_t)buf * 65536u + (uint32_t)sr * 128u;
        #pragma unroll
        for (int t = 0; t < 4; t++) {
            const __nv_bfloat16* s = tsrc[t] + k0;
            uint32_t db = dbase + (uint32_t)t * 16384u;
            #pragma unroll
            for (int c = 0; c < 2; c++) {
                uint32_t g = (uint32_t)(sq * 2 + c);
                uint32_t dst = db + ((g ^ swrow) << 4);
                CPASYNC16(dst, s + g * 8);
            }
        }
        asm volatile("cp.async.commit_group;" ::: "memory");
    };

    float acc[2][4][4];
    #pragma unroll
    for (int i = 0; i < 2; i++)
        #pragma unroll
        for (int j = 0; j < 4; j++)
            #pragma unroll
            for (int q = 0; q < 4; q++) acc[i][j][q] = 0.f;

    const int nt = K / 64;
    stage(0, 0);
    for (int it = 0; it < nt; it++) {
        if (it + 1 < nt) {
            stage((it + 1) & 1, (it + 1) * 64);
            asm volatile("cp.async.wait_group 1;" ::: "memory");
        } else {
            asm volatile("cp.async.wait_group 0;" ::: "memory");
        }
        __syncthreads();

        uint32_t tb = sbase + (uint32_t)(it & 1) * 65536u;
        #pragma unroll
        for (int ks = 0; ks < 4; ks++) {
            const int g0 = ks * 2;
            // A fragments (hi & lo), 2 m-tiles (warp covers 32 rows)
            uint32_t ah[2][4], al[2][4];
            {
                int row_off = ((lane >> 3) & 1) * 8 + (lane & 7);
                int g = g0 + (lane >> 4);
                #pragma unroll
                for (int mt = 0; mt < 2; mt++) {
                    int row = wm * 32 + mt * 16 + row_off;
                    uint32_t addr = tb + (uint32_t)row * 128u
                                  + (uint32_t)((g ^ (row & 7)) << 4);
                    LDM4(ah[mt], addr);
                    LDM4(al[mt], addr + 16384u);
                }
            }
            // B fragments (hi & lo), 4 n-tiles via 2 x4 loads each of hi/lo
            uint32_t bh[4][2], bl[4][2];
            {
                int grp = lane >> 3;
                #pragma unroll
                for (int p = 0; p < 2; p++) {
                    int tile = 2 * p + (grp >> 1);
                    int g = g0 + (grp & 1);
                    int nrow = wn * 32 + tile * 8 + (lane & 7);
                    uint32_t addr = tb + 32768u + (uint32_t)nrow * 128u
                                  + (uint32_t)((g ^ (nrow & 7)) << 4);
                    uint32_t r4[4];
                    LDM4(r4, addr);
                    bh[2*p][0] = r4[0]; bh[2*p][1] = r4[1];
                    bh[2*p+1][0] = r4[2]; bh[2*p+1][1] = r4[3];
                    LDM4(r4, addr + 16384u);
                    bl[2*p][0] = r4[0]; bl[2*p][1] = r4[1];
                    bl[2*p+1][0] = r4[2]; bl[2*p+1][1] = r4[3];
                }
            }
            // term-major: 8 independent MMAs per term (no short RAW chains)
            #pragma unroll
            for (int mt = 0; mt < 2; mt++)
                #pragma unroll
                for (int ntl = 0; ntl < 4; ntl++)
                    MMA16816(acc[mt][ntl], ah[mt], bh[ntl]);
            #pragma unroll
            for (int mt = 0; mt < 2; mt++)
                #pragma unroll
                for (int ntl = 0; ntl < 4; ntl++)
                    MMA16816(acc[mt][ntl], ah[mt], bl[ntl]);
            #pragma unroll
            for (int mt = 0; mt < 2; mt++)
                #pragma unroll
                for (int ntl = 0; ntl < 4; ntl++)
                    MMA16816(acc[mt][ntl], al[mt], bh[ntl]);
        }
        __syncthreads();
    }

    float s = 1.f, mu = 0.f, be = 0.f;
    if (EPI == EPI_COMB) { s = bn[0]*rsqrtf(bn[3]+1e-5f); mu = bn[2]; be = bn[1]; }
    #pragma unroll
    for (int mt = 0; mt < 2; mt++) {
        #pragma unroll
        for (int ntl = 0; ntl < 4; ntl++) {
            int row = m0 + wm*32 + mt*16 + (lane >> 2);
            int col = n0 + wn*32 + ntl*8 + (lane & 3)*2;
            if (EPI == EPI_C) {
                *(float2*)(Cf + (size_t)row*N + col) =
                    make_float2(acc[mt][ntl][0], acc[mt][ntl][1]);
                *(float2*)(Cf + (size_t)(row+8)*N + col) =
                    make_float2(acc[mt][ntl][2], acc[mt][ntl][3]);
            } else {
                #pragma unroll
                for (int q = 0; q < 4; q++) {
                    int r = row + (q >> 1)*8;
                    int c = col + (q & 1);
                    float v = acc[mt][ntl][q] + bias[c];
                    v = fmaxf((v - mu)*s + be, 0.f);
                    __nv_bfloat16 hv = __float2bfloat16(v);
                    Ohi[(size_t)r*HH + c] = hv;
                    Olo[(size_t)r*HH + c] = __float2bfloat16(v - __bfloat162float(hv));
                }
            }
        }
    }
}

__global__ __launch_bounds__(512) void mma_gemm(
    const __nv_bfloat16* __restrict__ Ahi, const __nv_bfloat16* __restrict__ Alo, int lda,
    const __nv_bfloat16* __restrict__ Bhi, const __nv_bfloat16* __restrict__ Blo, int ldb,
    int K, float* __restrict__ Cf, int N)
{
    extern __shared__ char sm[];
    mma_body<EPI_C>(sm, blockIdx.x, blockIdx.y, Ahi, Alo, lda, Bhi, Blo, ldb,
                    K, Cf, N, nullptr, nullptr, nullptr, nullptr);
}

// merged decoder launch: z=0 -> gh = h @ dec_Whh^T; z=1 (x<8) -> comb -> split o
__global__ __launch_bounds__(512) void comb_gh_kernel(
    const __nv_bfloat16* __restrict__ hhi, const __nv_bfloat16* __restrict__ hlo,
    const __nv_bfloat16* __restrict__ whh_hi, const __nv_bfloat16* __restrict__ whh_lo,
    float* __restrict__ gh,
    const __nv_bfloat16* __restrict__ chi, const __nv_bfloat16* __restrict__ clo,
    const __nv_bfloat16* __restrict__ wc_hi, const __nv_bfloat16* __restrict__ wc_lo,
    const float* __restrict__ comb_b, const float* __restrict__ bn2,
    __nv_bfloat16* __restrict__ ohi, __nv_bfloat16* __restrict__ olo)
{
    extern __shared__ char sm[];
    if (blockIdx.z == 0) {
        mma_body<EPI_C>(sm, blockIdx.x, blockIdx.y, hhi, hlo, HH, whh_hi, whh_lo, HH,
                        HH, gh, 3*HH, nullptr, nullptr, nullptr, nullptr);
    } else {
        if (blockIdx.x >= HH/128) return;
        mma_body<EPI_COMB>(sm, blockIdx.x, blockIdx.y, chi, clo, CATW, wc_hi, wc_lo, CATW,
                           CATW, nullptr, HH, comb_b, bn2, ohi, olo);
    }
}

// ---------------- weight splits ----------------------------------------------
__device__ __forceinline__ void split_seg(const float* src, __nv_bfloat16* hi,
                                          __nv_bfloat16* lo, int idx, int K, int Kpad)
{
    int r = idx / Kpad, k = idx - r*Kpad;
    float v = (k < K) ? src[(size_t)r*K + k] : 0.f;
    __nv_bfloat16 h = __float2bfloat16(v);
    hi[idx] = h;
    lo[idx] = __float2bfloat16(v - __bfloat162float(h));
}

__global__ void split_a_kernel(const float* __restrict__ w_eih, const float* __restrict__ w_ehh)
{
    int idx = blockIdx.x*blockDim.x + threadIdx.x;
    const int n0 = 3*HH*EEP, n1 = 3*HH*HH;
    if (idx < n0) split_seg(w_eih, g_wencih_hi, g_wencih_lo, idx, EE, EEP);
    else if (idx < n0 + n1) split_seg(w_ehh, g_wenchh_hi, g_wenchh_lo, idx - n0, HH, HH);
}

__global__ void split_b_kernel(const float* __restrict__ w_dih, const float* __restrict__ w_dhh,
                               const float* __restrict__ w_cmb)
{
    int idx = blockIdx.x*blockDim.x + threadIdx.x;
    const int n0 = 3*HH*HH, n1 = 3*HH*HH, n2 = HH*CATW;
    if (idx < n0) split_seg(w_dih, g_wdecih_hi, g_wdecih_lo, idx, HH, HH);
    else if (idx < n0+n1) split_seg(w_dhh, g_wdechh_hi, g_wdechh_lo, idx - n0, HH, HH);
    else if (idx < n0+n1+n2) split_seg(w_cmb, g_wcomb_hi, g_wcomb_lo, idx - n0 - n1, CATW, CATW);
}

// ---------------- small / fused kernels --------------------------------------
__global__ void init_kernel()
{
    int idx = blockIdx.x*blockDim.x + threadIdx.x;
    if (idx < BB*HH) {
        g_h[idx] = 0.f;
        g_h_hi[idx] = __float2bfloat16(0.f);
        g_h_lo[idx] = __float2bfloat16(0.f);
    }
    if (idx < BB) g_inp[idx] = TT;
}

__global__ void embed_renorm_kernel(const int* __restrict__ tokens,
                                    const float* __restrict__ w2v)
{
    int row = blockIdx.x;
    int tok = tokens[row];
    const float* src = w2v + (size_t)tok*EE;
    __shared__ float red[128];
    float ss = 0.f;
    for (int k = threadIdx.x; k < EE; k += blockDim.x) { float v = src[k]; ss += v*v; }
    red[threadIdx.x] = ss; __syncthreads();
    for (int s = blockDim.x>>1; s>0; s>>=1) {
        if (threadIdx.x < s) red[threadIdx.x] += red[threadIdx.x+s];
        __syncthreads();
    }
    float sc = fminf(1.f, 10.f/(sqrtf(red[0])+1e-7f));
    for (int k = threadIdx.x; k < EE; k += blockDim.x) {
        float v = src[k]*sc;
        __nv_bfloat16 h = __float2bfloat16(v);
        g_x_hi[(size_t)row*EEP + k] = h;
        g_x_lo[(size_t)row*EEP + k] = __float2bfloat16(v - __bfloat162float(h));
    }
    for (int k = EE + threadIdx.x; k < EEP; k += blockDim.x) {
        g_x_hi[(size_t)row*EEP + k] = __float2bfloat16(0.f);
        g_x_lo[(size_t)row*EEP + k] = __float2bfloat16(0.f);
    }
}

__global__ void gru_kernel(const float* __restrict__ gi0, int gi_stride,
                           const float* __restrict__ bih,
                           const float* __restrict__ gh0,
                           const float* __restrict__ bhh,
                           float* __restrict__ h,
                           float* __restrict__ outp, int out_stride)
{
    int idx = blockIdx.x*blockDim.x + threadIdx.x;
    if (idx >= BB*HH) return;
    int b = idx / HH, j = idx - b*HH;
    const float* p = gi0 + (size_t)b*gi_stride;
    float i_r = p[j], i_z = p[HH+j], i_n = p[2*HH+j];
    if (bih) { i_r += bih[j]; i_z += bih[HH+j]; i_n += bih[2*HH+j]; }
    const float* q = gh0 + (size_t)b*3*HH;
    float h_r = q[j]      + bhh[j];
    float h_z = q[HH+j]   + bhh[HH+j];
    float h_n = q[2*HH+j] + bhh[2*HH+j];
    float r = sigmoidf_(i_r + h_r);
    float z = sigmoidf_(i_z + h_z);
    float n = tanhf(i_n + r*h_n);
    float hn = (1.f - z)*n + z*h[idx];
    h[idx] = hn;
    __nv_bfloat16 hv = __float2bfloat16(hn);
    g_h_hi[idx] = hv;
    g_h_lo[idx] = __float2bfloat16(hn - __bfloat162float(hv));
    if (outp) outp[(size_t)b*out_stride + j] = hn;
}

// merged: [log_softmax+argmax of step lsm_t] then [embedding+attn+applied next step]
__global__ __launch_bounds__(256) void lsm_attn_kernel(
    const float* __restrict__ dec_emb,
    const float* __restrict__ attn_W, const float* __restrict__ attn_b,
    const float* __restrict__ Wt, const float* __restrict__ ob,
    const float* __restrict__ bn, float* __restrict__ out,
    int lsm_t, int do_attn)
{
    constexpr int CH = 64;
    __shared__ float sh[HH];
    __shared__ float Ws[TT][CH+1];
    __shared__ float red[256];
    __shared__ int   redi[128];
    __shared__ float semb[DD];
    __shared__ float saw[32];

    int b = blockIdx.x, tid = threadIdx.x;
    for (int k = tid; k < HH; k += 256) sh[k] = g_h[(size_t)b*HH + k];
    __syncthreads();

    int token;
    if (lsm_t >= 0) {
        int v = tid & 127, half = tid >> 7;
        float s = bn[0]*rsqrtf(bn[3]+1e-5f);
        float c0 = bn[1] - bn[2]*s;
        float acc = 0.f;
        for (int k0 = 0; k0 < HH; k0 += CH) {
            __syncthreads();
            for (int i = tid; i < TT*CH; i += 256) {
                int r = i >> 6, c = i & 63;
                Ws[r][c] = Wt[(size_t)r*HH + k0 + c];
            }
            __syncthreads();
            const int kb = half*32;
            #pragma unroll
            for (int k = 0; k < 32; k++)
                acc += (sh[k0 + kb + k]*s + c0) * Ws[v][kb + k];
        }
        __syncthreads();
        red[tid] = acc; __syncthreads();
        float x = 0.f;
        if (tid < 128) x = red[tid] + red[tid+128] + ob[tid];
        __syncthreads();
        if (tid < 128) { red[tid] = x; redi[tid] = tid; }
        __syncthreads();
        for (int st = 64; st > 0; st >>= 1) {
            if (tid < st) {
                if (red[tid+st] > red[tid]) { red[tid]=red[tid+st]; redi[tid]=redi[tid+st]; }
            }
            __syncthreads();
        }
        float m = red[0]; int am = redi[0];
        __syncthreads();
        red[tid] = (tid < 128) ? expf(x - m) : 0.f;
        __syncthreads();
        for (int st = 128; st > 0; st >>= 1) { if (tid<st) red[tid]+=red[tid+st]; __syncthreads(); }
        float lse = logf(red[0]);
        if (tid < 128) out[((size_t)b*LL + lsm_t)*TT + tid] = x - m - lse;
        token = am;
        __syncthreads();
    } else {
        token = g_inp[b];
    }

    if (!do_attn) return;

    float val = dec_emb[(size_t)token*DD + tid];
    red[tid] = val*val; __syncthreads();
    for (int s=128; s>0; s>>=1) { if (tid<s) red[tid]+=red[tid+s]; __syncthreads(); }
    float sc = fminf(1.f, 1.f/(sqrtf(red[0])+1e-7f));
    float e = val*sc;
    semb[tid] = e;
    {
        __nv_bfloat16 h = __float2bfloat16(e);
        g_cat_hi[(size_t)b*CATW + tid] = h;
        g_cat_lo[(size_t)b*CATW + tid] = __float2bfloat16(e - __bfloat162float(h));
    }
    __syncthreads();

    int warp = tid>>5, lane = tid&31;
    for (int l = warp; l < LL; l += 8) {
        const float* w = attn_W + (size_t)l*CATW;
        float acc = 0.f;
        for (int k = lane; k < DD; k += 32) acc += semb[k]*w[k];
        for (int k = lane; k < HH; k += 32) acc += sh[k]*w[DD+k];
        for (int o=16;o;o>>=1) acc += __shfl_xor_sync(0xffffffffu, acc, o);
        if (lane==0) saw[l] = acc + attn_b[l];
    }
    __syncthreads();
    if (warp==0) {
        float v = (lane<LL)? saw[lane] : -1e30f;
        float m = v;
        for (int o=16;o;o>>=1) m = fmaxf(m, __shfl_xor_sync(0xffffffffu, m, o));
        float ex = (lane<LL)? expf(v-m) : 0.f;
        float sm = ex;
        for (int o=16;o;o>>=1) sm += __shfl_xor_sync(0xffffffffu, sm, o);
        if (lane<LL) saw[lane] = ex/sm;
    }
    __syncthreads();

    const float* eo = g_enc_out + (size_t)b*LL*HH;
    for (int j = tid; j < HH; j += 256) {
        float acc = 0.f;
        #pragma unroll
        for (int l=0;l<LL;l++) acc += saw[l]*eo[(size_t)l*HH + j];
        __nv_bfloat16 h = __float2bfloat16(acc);
        g_cat_hi[(size_t)b*CATW + DD + j] = h;
        g_cat_lo[(size_t)b*CATW + DD + j] = __float2bfloat16(acc - __bfloat162float(h));
    }
}

// ---------------- launch ------------------------------------------------------
extern "C" void kernel_launch(void* const* d_in, const int* in_sizes, int n_in,
                              void* d_out, int out_size)
{
    const int*   tokens  = (const int*)  d_in[0];
    const float* w2v     = (const float*)d_in[1];
    const float* enc_Wih = (const float*)d_in[2];
    const float* enc_Whh = (const float*)d_in[3];
    const float* enc_bih = (const float*)d_in[4];
    const float* enc_bhh = (const float*)d_in[5];
    const float* dec_emb = (const float*)d_in[6];
    const float* attn_W  = (const float*)d_in[7];
    const float* attn_b  = (const float*)d_in[8];
    const float* comb_W  = (const float*)d_in[9];
    const float* comb_b  = (const float*)d_in[10];
    const float* dec_Wih = (const float*)d_in[11];
    const float* dec_Whh = (const float*)d_in[12];
    const float* dec_bih = (const float*)d_in[13];
    const float* dec_bhh = (const float*)d_in[14];
    const float* out_W   = (const float*)d_in[15];
    const float* out_b   = (const float*)d_in[16];
    const float* bn1     = (const float*)d_in[17];
    const float* bn2     = (const float*)d_in[18];
    float* out = (float*)d_out;

    __nv_bfloat16 *pxh, *pxl, *phh, *phl, *pch, *pcl, *poh, *pol;
    __nv_bfloat16 *pw_eih_h, *pw_eih_l, *pw_ehh_h, *pw_ehh_l;
    __nv_bfloat16 *pw_dih_h, *pw_dih_l, *pw_dhh_h, *pw_dhh_l, *pw_cmb_h, *pw_cmb_l;
    float *pgi_all, *penc_out, *ph, *pgh, *pgi_dec;
    cudaGetSymbolAddress((void**)&pxh, g_x_hi);       cudaGetSymbolAddress((void**)&pxl, g_x_lo);
    cudaGetSymbolAddress((void**)&phh, g_h_hi);       cudaGetSymbolAddress((void**)&phl, g_h_lo);
    cudaGetSymbolAddress((void**)&pch, g_cat_hi);     cudaGetSymbolAddress((void**)&pcl, g_cat_lo);
    cudaGetSymbolAddress((void**)&poh, g_o_hi);       cudaGetSymbolAddress((void**)&pol, g_o_lo);
    cudaGetSymbolAddress((void**)&pw_eih_h, g_wencih_hi); cudaGetSymbolAddress((void**)&pw_eih_l, g_wencih_lo);
    cudaGetSymbolAddress((void**)&pw_ehh_h, g_wenchh_hi); cudaGetSymbolAddress((void**)&pw_ehh_l, g_wenchh_lo);
    cudaGetSymbolAddress((void**)&pw_dih_h, g_wdecih_hi); cudaGetSymbolAddress((void**)&pw_dih_l, g_wdecih_lo);
    cudaGetSymbolAddress((void**)&pw_dhh_h, g_wdechh_hi); cudaGetSymbolAddress((void**)&pw_dhh_l, g_wdechh_lo);
    cudaGetSymbolAddress((void**)&pw_cmb_h, g_wcomb_hi);  cudaGetSymbolAddress((void**)&pw_cmb_l, g_wcomb_lo);
    cudaGetSymbolAddress((void**)&pgi_all,  g_gi_all);
    cudaGetSymbolAddress((void**)&penc_out, g_enc_out);
    cudaGetSymbolAddress((void**)&ph,       g_h);
    cudaGetSymbolAddress((void**)&pgh,      g_gh);
    cudaGetSymbolAddress((void**)&pgi_dec,  g_gi_dec);

    const int SMEM_MMA = 2 * 4 * 16384;   // 128 KB
    cudaFuncSetAttribute(mma_gemm,       cudaFuncAttributeMaxDynamicSharedMemorySize, SMEM_MMA);
    cudaFuncSetAttribute(comb_gh_kernel, cudaFuncAttributeMaxDynamicSharedMemorySize, SMEM_MMA);

    const int EW = 2048;

    // launch order: index 3 = encoder recurrent GEMM (ncu -s 5 lands on my index 3)
    init_kernel<<<EW, 256>>>();                                           // 0
    split_a_kernel<<<(3*HH*EEP + 3*HH*HH + 255)/256, 256>>>(enc_Wih, enc_Whh);   // 1
    split_b_kernel<<<(2*3*HH*HH + HH*CATW + 255)/256, 256>>>(dec_Wih, dec_Whh, comb_W); // 2
    mma_gemm<<<dim3(3*HH/128, BB/128), 512, SMEM_MMA>>>(                  // 3 (profiled)
        phh, phl, HH, pw_ehh_h, pw_ehh_l, HH, HH, pgh, 3*HH);
    embed_renorm_kernel<<<BL, 128>>>(tokens, w2v);                        // 4
    mma_gemm<<<dim3(3*HH/128, BL/128), 512, SMEM_MMA>>>(                  // 5
        pxh, pxl, EEP, pw_eih_h, pw_eih_l, EEP, EEP, pgi_all, 3*HH);
    gru_kernel<<<EW, 256>>>(pgi_all, LL*3*HH, enc_bih,                    // 6 (t=0)
                            pgh, enc_bhh, ph, penc_out, LL*HH);

    // encoder recurrence t=1..24
    for (int t = 1; t < LL; t++) {
        mma_gemm<<<dim3(3*HH/128, BB/128), 512, SMEM_MMA>>>(
            phh, phl, HH, pw_ehh_h, pw_ehh_l, HH, HH, pgh, 3*HH);
        gru_kernel<<<EW, 256>>>(pgi_all + (size_t)t*3*HH, LL*3*HH, enc_bih,
                                pgh, enc_bhh, ph, penc_out + (size_t)t*HH, LL*HH);
    }

    // greedy attention decoder
    lsm_attn_kernel<<<BB, 256>>>(dec_emb, attn_W, attn_b, out_W, out_b, bn1, out, -1, 1);
    for (int t = 0; t < LL; t++) {
        comb_gh_kernel<<<dim3(3*HH/128, BB/128, 2), 512, SMEM_MMA>>>(
            phh, phl, pw_dhh_h, pw_dhh_l, pgh,
            pch, pcl, pw_cmb_h, pw_cmb_l, comb_b, bn2, poh, pol);
        mma_gemm<<<dim3(3*HH/128, BB/128), 512, SMEM_MMA>>>(
            poh, pol, HH, pw_dih_h, pw_dih_l, HH, HH, pgi_dec, 3*HH);
        gru_kernel<<<EW, 256>>>(pgi_dec, 3*HH, dec_bih, pgh, dec_bhh, ph, nullptr, 0);
        lsm_attn_kernel<<<BB, 256>>>(dec_emb, attn_W, attn_b, out_W, out_b, bn1, out,
                                     t, (t < LL-1) ? 1 : 0);
    }
}